// round 10
// baseline (speedup 1.0000x reference)
#include <cuda_runtime.h>
#include <cuda_bf16.h>
#include <math.h>
#include <stdint.h>

#define D    256
#define R    8
#define NG   64
#define NMAX 50176          // 392*128
#define NBLK 392
#define EPS  1e-5f
#define KTOT 2304           // (R+1)*D
#define NST  72             // KTOT / 32
#define BM   128
#define EMAX 1048576

// padded tile geometry (floats); row stride 40 -> LDS.64 conflict-free
#define LDAf  40
#define ATILE (128 * LDAf)              // 5120 floats = 20480 B
#define BTILE (256 * LDAf)              // 10240 floats = 40960 B
#define OA    0
#define OB    20480
#define STG   61440                     // bytes per stage
#define NSTAGE 3
#define SMEM_TOTAL (NSTAGE * STG + 64)  // 184384 B

// ---------------- static device scratch ----------------
__device__ float  g_A[(size_t)NBLK * NST * ATILE];   // tile-major, col-permuted tf32
__device__ float  g_B[(size_t)NST * BTILE];
__device__ float  g_X0[(size_t)NMAX * D];
__device__ float  g_X1[(size_t)NMAX * D];
__device__ int    g_cnt[NMAX * R];
__device__ int    g_off[NMAX * R];
__device__ int    g_pos[NMAX * R];
__device__ int    g_cursor[1];
__device__ int    g_esrc[EMAX];
__device__ double g_lnstats[3][2];
__device__ float  g_pool[NG * D];
__device__ int    g_gcnt[NG];

// ---------------- helpers ----------------
__device__ __forceinline__ uint32_t smem_u32(const void* p) {
    return (uint32_t)__cvta_generic_to_shared((void*)p);
}
__device__ __forceinline__ void red_add_v4(float* addr, float4 v) {
    asm volatile("red.global.add.v4.f32 [%0], {%1,%2,%3,%4};"
                 :: "l"(addr), "f"(v.x), "f"(v.y), "f"(v.z), "f"(v.w) : "memory");
}
__device__ __forceinline__ void mma_tf32(float (&d)[4], uint32_t a0, uint32_t a1,
                                         uint32_t a2, uint32_t a3,
                                         uint32_t b0, uint32_t b1) {
    asm volatile(
        "mma.sync.aligned.m16n8k8.row.col.f32.tf32.tf32.f32 "
        "{%0,%1,%2,%3}, {%4,%5,%6,%7}, {%8,%9}, {%0,%1,%2,%3};"
        : "+f"(d[0]), "+f"(d[1]), "+f"(d[2]), "+f"(d[3])
        : "r"(a0), "r"(a1), "r"(a2), "r"(a3), "r"(b0), "r"(b1));
}
__device__ __forceinline__ uint32_t f2tf(float f) {
    uint32_t u;
    asm("cvt.rna.tf32.f32 %0, %1;" : "=r"(u) : "f"(f));
    return u;
}
__device__ __forceinline__ void mbar_init(uint32_t mb, uint32_t cnt) {
    asm volatile("mbarrier.init.shared.b64 [%0], %1;" :: "r"(mb), "r"(cnt) : "memory");
}
__device__ __forceinline__ void mbar_expect_tx(uint32_t mb, uint32_t bytes) {
    asm volatile("mbarrier.arrive.expect_tx.shared.b64 _, [%0], %1;"
                 :: "r"(mb), "r"(bytes) : "memory");
}
__device__ __forceinline__ void mbar_wait(uint32_t mb, uint32_t ph) {
    asm volatile(
        "{\n\t.reg .pred P;\n\t"
        "LW%=:\n\t"
        "mbarrier.try_wait.parity.acquire.cta.shared::cta.b64 P, [%0], %1, 0x989680;\n\t"
        "@P bra LD%=;\n\t"
        "bra LW%=;\n\t"
        "LD%=:\n\t}"
        :: "r"(mb), "r"(ph) : "memory");
}
__device__ __forceinline__ void bulk_g2s(uint32_t dst, const void* src,
                                         uint32_t bytes, uint32_t mb) {
    asm volatile(
        "cp.async.bulk.shared::cta.global.mbarrier::complete_tx::bytes [%0], [%1], %2, [%3];"
        :: "r"(dst), "l"(src), "r"(bytes), "r"(mb) : "memory");
}
__device__ __forceinline__ void ln_params(const double* st, int M, float& mu, float& rs) {
    double m = st[0] / (double)M;
    double var = st[1] / (double)M - m * m;
    mu = (float)m;
    rs = 1.0f / ((float)sqrt(fmax(var, 0.0)) + EPS);
}

// ---------------- CSR build ----------------
__global__ void count_kernel(const int* __restrict__ dst, const int* __restrict__ et, int E) {
    int i = blockIdx.x * blockDim.x + threadIdx.x;
    if (blockIdx.x == 0) {
        if (threadIdx.x < 6) ((double*)g_lnstats)[threadIdx.x] = 0.0;
        if (threadIdx.x == 6) g_cursor[0] = 0;
    }
    if (i < E) atomicAdd(&g_cnt[dst[i] * R + et[i]], 1);
}

__global__ void scan_atomic(int L) {
    __shared__ int sh[256];
    __shared__ int sbase;
    int tid = threadIdx.x;
    int i = blockIdx.x * 256 + tid;
    int v = (i < L) ? g_cnt[i] : 0;
    sh[tid] = v; __syncthreads();
    #pragma unroll
    for (int o = 1; o < 256; o <<= 1) {
        int t = (tid >= o) ? sh[tid - o] : 0;
        __syncthreads();
        sh[tid] += t;
        __syncthreads();
    }
    if (tid == 255) sbase = atomicAdd(&g_cursor[0], sh[255]);
    __syncthreads();
    if (i < L) {
        int o = sbase + sh[tid] - v;
        g_off[i] = o;
        g_pos[i] = o;
    }
}

__global__ void place_kernel(const int* __restrict__ src, const int* __restrict__ dst,
                             const int* __restrict__ et, int E) {
    int e = blockIdx.x * blockDim.x + threadIdx.x;
    if (e < E) {
        int seg = dst[e] * R + et[e];
        int p = atomicAdd(&g_pos[seg], 1);
        g_esrc[p] = src[e];
    }
}

// ---------------- weight prep: transpose + tf32 + column permutation ----------------
__global__ void prep_B(const float* __restrict__ Wrel, const float* __restrict__ Wroot) {
    __shared__ float s[32][33];
    int k0 = blockIdx.x * 32, j0 = blockIdx.y * 32;
    int kt = blockIdx.x;
    int tx = threadIdx.x;
    for (int i = threadIdx.y; i < 32; i += 8) {
        int k = k0 + i;
        const float* row = (k < R * D) ? (Wrel + (size_t)k * D)
                                       : (Wroot + (size_t)(k - R * D) * D);
        s[i][tx] = row[j0 + tx];
    }
    __syncthreads();
    // permuted k-position: pos = kc*8 + (j&3)*2 + (j>>2), j = tx&7, kc = tx>>3
    int pos = (tx & 24) + (tx & 3) * 2 + ((tx >> 2) & 1);
    for (int i = threadIdx.y; i < 32; i += 8) {
        int j = j0 + i;
        uint32_t u = f2tf(s[tx][i]);
        ((uint32_t*)g_B)[(size_t)kt * BTILE + j * LDAf + pos] = u;
    }
}

// ---------------- aggregate: warp per (node, rel); 2-edge unroll; permuted out ----------------
__global__ __launch_bounds__(256) void aggregate(
    const float* __restrict__ x,
    const float* __restrict__ lnw, const float* __restrict__ lnb,
    const double* __restrict__ stats, int M, int Nn)
{
    int wid = threadIdx.x >> 5, lane = threadIdx.x & 31;
    int seg = blockIdx.x * 8 + wid;
    int n = seg >> 3, r = seg & 7;
    int cnt = g_cnt[seg];
    int off = g_off[seg];
    float a[8] = {0, 0, 0, 0, 0, 0, 0, 0};
    float b[8] = {0, 0, 0, 0, 0, 0, 0, 0};
    if (cnt > 0) {
        int i = 0;
        for (; i + 2 <= cnt; i += 2) {
            int sa = __ldg(&g_esrc[off + i]);
            int sb = __ldg(&g_esrc[off + i + 1]);
            const float4* xa = (const float4*)(x + (size_t)sa * D + lane * 8);
            const float4* xb = (const float4*)(x + (size_t)sb * D + lane * 8);
            float4 p0 = __ldg(xa), p1 = __ldg(xa + 1);
            float4 q0 = __ldg(xb), q1 = __ldg(xb + 1);
            a[0] += p0.x; a[1] += p0.y; a[2] += p0.z; a[3] += p0.w;
            a[4] += p1.x; a[5] += p1.y; a[6] += p1.z; a[7] += p1.w;
            b[0] += q0.x; b[1] += q0.y; b[2] += q0.z; b[3] += q0.w;
            b[4] += q1.x; b[5] += q1.y; b[6] += q1.z; b[7] += q1.w;
        }
        if (i < cnt) {
            int sa = __ldg(&g_esrc[off + i]);
            const float4* xa = (const float4*)(x + (size_t)sa * D + lane * 8);
            float4 p0 = __ldg(xa), p1 = __ldg(xa + 1);
            a[0] += p0.x; a[1] += p0.y; a[2] += p0.z; a[3] += p0.w;
            a[4] += p1.x; a[5] += p1.y; a[6] += p1.z; a[7] += p1.w;
        }
        #pragma unroll
        for (int q = 0; q < 8; q++) a[q] += b[q];
        float sc = 1.0f / (float)cnt;
        #pragma unroll
        for (int q = 0; q < 8; q++) a[q] *= sc;
        if (stats != nullptr) {
            float mu, rs;
            ln_params(stats, M, mu, rs);
            int c0 = lane * 8;
            #pragma unroll
            for (int q = 0; q < 8; q++)
                a[q] = lnw[c0 + q] * ((a[q] - mu) * rs) + lnb[c0 + q];
        }
    }
    uint32_t w[8];
    #pragma unroll
    for (int q = 0; q < 8; q++) w[q] = f2tf(a[q]);
    int blk = n >> 7, row = n & 127;
    int kt = r * 8 + (lane >> 2);
    uint32_t* o = (uint32_t*)g_A + ((size_t)blk * NST + kt) * ATILE
                + row * LDAf + (lane & 3) * 8;
    // permuted order within the 8-column group
    *(uint4*)o       = make_uint4(w[0], w[4], w[1], w[5]);
    *(uint4*)(o + 4) = make_uint4(w[2], w[6], w[3], w[7]);
}

// ---------------- x -> tf32 tiles kt 64..71; lazy-LN; permuted ----------------
__global__ void xconvert(const float* __restrict__ x,
                         const float* __restrict__ lnw, const float* __restrict__ lnb,
                         const double* __restrict__ stats, int M, int Nn)
{
    int idx = blockIdx.x * blockDim.x + threadIdx.x;
    int n = idx >> 5, c8 = (idx & 31) * 8;
    if (n >= NMAX) return;
    float v[8] = {0, 0, 0, 0, 0, 0, 0, 0};
    if (n < Nn) {
        float4 p0 = *(const float4*)(x + (size_t)n * D + c8);
        float4 p1 = *(const float4*)(x + (size_t)n * D + c8 + 4);
        v[0] = p0.x; v[1] = p0.y; v[2] = p0.z; v[3] = p0.w;
        v[4] = p1.x; v[5] = p1.y; v[6] = p1.z; v[7] = p1.w;
        if (stats != nullptr) {
            float mu, rs;
            ln_params(stats, M, mu, rs);
            #pragma unroll
            for (int q = 0; q < 8; q++)
                v[q] = lnw[c8 + q] * ((v[q] - mu) * rs) + lnb[c8 + q];
        }
    }
    uint32_t w[8];
    #pragma unroll
    for (int q = 0; q < 8; q++) w[q] = f2tf(v[q]);
    int blk = n >> 7, row = n & 127;
    int kt = 64 + (c8 >> 5);
    uint32_t* o = (uint32_t*)g_A + ((size_t)blk * NST + kt) * ATILE
                + row * LDAf + (c8 & 31);
    *(uint4*)o       = make_uint4(w[0], w[4], w[1], w[5]);
    *(uint4*)(o + 4) = make_uint4(w[2], w[6], w[3], w[7]);
}

// ---------------- tf32 GEMM: bulk-DMA, LDS.64 fragments, 8 warps 64x64 ----------------
__global__ __launch_bounds__(256) void rgcn_hmma(
    const float* __restrict__ Xcur,
    const float* __restrict__ bconv,
    float* __restrict__ Xnext, int Nn,
    const float* __restrict__ pw, const float* __restrict__ pb,
    const double* __restrict__ statsPrev,
    double* __restrict__ statsOut, int M)
{
    extern __shared__ char sm[];
    uint32_t sbase = smem_u32(sm);
    uint32_t mbb = sbase + NSTAGE * STG;
    int tid = threadIdx.x, lane = tid & 31, wid = tid >> 5;
    int wm = wid & 1, wn = wid >> 1;
    int row0 = blockIdx.x * BM;
    const float* gAblk = g_A + (size_t)blockIdx.x * NST * ATILE;

    if (tid == 0) {
        #pragma unroll
        for (int s = 0; s < NSTAGE; s++) mbar_init(mbb + s * 8, 1);
    }
    __syncthreads();
    if (tid == 0) {
        #pragma unroll
        for (int s = 0; s < NSTAGE; s++) {
            mbar_expect_tx(mbb + s * 8, STG);
            bulk_g2s(sbase + s * STG + OA, gAblk + (size_t)s * ATILE, 20480, mbb + s * 8);
            bulk_g2s(sbase + s * STG + OB, g_B + (size_t)s * BTILE, 40960, mbb + s * 8);
        }
    }

    float acc[4][8][4];
    #pragma unroll
    for (int i = 0; i < 4; i++)
        #pragma unroll
        for (int j = 0; j < 8; j++)
            #pragma unroll
            for (int q = 0; q < 4; q++) acc[i][j][q] = 0.f;

    int fr = lane >> 2, fc = lane & 3;

    #pragma unroll 1
    for (int kt = 0; kt < NST; kt++) {
        int b = kt % NSTAGE;
        mbar_wait(mbb + b * 8, (kt / 3) & 1);

        const float* As = (const float*)(sm + b * STG + OA);
        const float* Bs = (const float*)(sm + b * STG + OB);

        #pragma unroll
        for (int kc = 0; kc < 4; kc++) {
            float2 a0[4], a1[4];
            #pragma unroll
            for (int mi = 0; mi < 4; mi++) {
                const float* Ab = As + (wm * 64 + mi * 16 + fr) * LDAf + kc * 8 + fc * 2;
                a0[mi] = *(const float2*)Ab;
                a1[mi] = *(const float2*)(Ab + 8 * LDAf);
            }
            #pragma unroll
            for (int nj = 0; nj < 8; nj++) {
                const float* Bb = Bs + (wn * 64 + nj * 8 + fr) * LDAf + kc * 8 + fc * 2;
                float2 bv = *(const float2*)Bb;
                uint32_t b0 = __float_as_uint(bv.x), b1 = __float_as_uint(bv.y);
                #pragma unroll
                for (int mi = 0; mi < 4; mi++)
                    mma_tf32(acc[mi][nj],
                             __float_as_uint(a0[mi].x), __float_as_uint(a1[mi].x),
                             __float_as_uint(a0[mi].y), __float_as_uint(a1[mi].y),
                             b0, b1);
            }
        }
        __syncthreads();
        if (tid == 0 && kt + NSTAGE < NST) {
            mbar_expect_tx(mbb + b * 8, STG);
            bulk_g2s(sbase + b * STG + OA, gAblk + (size_t)(kt + NSTAGE) * ATILE,
                     20480, mbb + b * 8);
            bulk_g2s(sbase + b * STG + OB, g_B + (size_t)(kt + NSTAGE) * BTILE,
                     40960, mbb + b * 8);
        }
    }

    // ---- epilogue: bias + residual(affine) + relu + stats ----
    float mu = 0.f, rs = 0.f;
    bool ln = (statsPrev != nullptr);
    if (ln) ln_params(statsPrev, M, mu, rs);

    float ps = 0.f, pq = 0.f;
    #pragma unroll
    for (int mi = 0; mi < 4; mi++) {
        #pragma unroll
        for (int half = 0; half < 2; half++) {
            int n = row0 + wm * 64 + mi * 16 + fr + half * 8;
            if (n >= Nn) continue;
            #pragma unroll
            for (int nj = 0; nj < 8; nj++) {
                int col = wn * 64 + nj * 8 + fc * 2;
                float2 xv = *(const float2*)(Xcur + (size_t)n * D + col);
                float2 bv = *(const float2*)(bconv + col);
                if (ln) {
                    float2 wv = *(const float2*)(pw + col);
                    float2 bb = *(const float2*)(pb + col);
                    xv.x = wv.x * ((xv.x - mu) * rs) + bb.x;
                    xv.y = wv.y * ((xv.y - mu) * rs) + bb.y;
                }
                float2 o;
                o.x = fmaxf(acc[mi][nj][half * 2 + 0] + bv.x + xv.x, 0.f);
                o.y = fmaxf(acc[mi][nj][half * 2 + 1] + bv.y + xv.y, 0.f);
                *(float2*)(Xnext + (size_t)n * D + col) = o;
                ps += o.x + o.y;
                pq += o.x * o.x + o.y * o.y;
            }
        }
    }
    if (statsOut != nullptr) {
        #pragma unroll
        for (int o = 16; o > 0; o >>= 1) {
            ps += __shfl_down_sync(0xffffffffu, ps, o);
            pq += __shfl_down_sync(0xffffffffu, pq, o);
        }
        if (lane == 0) {
            atomicAdd(&statsOut[0], (double)ps);
            atomicAdd(&statsOut[1], (double)pq);
        }
    }
}

// ---------------- global mean pool + head ----------------
__global__ void pool_cnt(const int* __restrict__ batch, int Nn) {
    int i = blockIdx.x * blockDim.x + threadIdx.x;
    if (i < Nn) atomicAdd(&g_gcnt[batch[i]], 1);
}
__global__ void pool_sum(const float* __restrict__ X, const int* __restrict__ batch, int Nn) {
    int idx = blockIdx.x * blockDim.x + threadIdx.x;
    if (idx >= Nn * (D / 4)) return;
    int n = idx >> 6, c = idx & 63;
    float4 v = ((const float4*)X)[(size_t)n * (D / 4) + c];
    red_add_v4(g_pool + batch[n] * D + c * 4, v);
}
__global__ void head_kernel(const float* __restrict__ W1, const float* __restrict__ b1,
                            const float* __restrict__ W2, const float* __restrict__ b2,
                            const float* __restrict__ W3, const float* __restrict__ b3,
                            float* __restrict__ out) {
    __shared__ float g[D], h1[D], h2[D];
    int bg = blockIdx.x, j = threadIdx.x;
    float c = fmaxf((float)g_gcnt[bg], 1.f);
    g[j] = g_pool[bg * D + j] / c;
    __syncthreads();
    float acc = b1[j];
    for (int k = 0; k < D; k++) acc = fmaf(g[k], W1[k * D + j], acc);
    h1[j] = fmaxf(acc, 0.f);
    __syncthreads();
    acc = b2[j];
    for (int k = 0; k < D; k++) acc = fmaf(h1[k], W2[k * D + j], acc);
    h2[j] = fmaxf(acc, 0.f);
    __syncthreads();
    if (j < 4) {
        acc = b3[j];
        for (int k = 0; k < D; k++) acc = fmaf(h2[k], W3[k * 4 + j], acc);
        out[bg * 4 + j] = acc;
    }
}

// ---------------- launch ----------------
extern "C" void kernel_launch(void* const* d_in, const int* in_sizes, int n_in,
                              void* d_out, int out_size) {
    const float* x      = (const float*)d_in[0];
    const int*   ei     = (const int*)d_in[1];
    const int*   et     = (const int*)d_in[2];
    const int*   batch  = (const int*)d_in[3];
    const float* W_rel  = (const float*)d_in[4];
    const float* W_root = (const float*)d_in[5];
    const float* b_conv = (const float*)d_in[6];
    const float* ln_w   = (const float*)d_in[7];
    const float* ln_b   = (const float*)d_in[8];
    const float* W1 = (const float*)d_in[9];
    const float* b1 = (const float*)d_in[10];
    const float* W2 = (const float*)d_in[11];
    const float* b2 = (const float*)d_in[12];
    const float* W3 = (const float*)d_in[13];
    const float* b3 = (const float*)d_in[14];

    int E  = in_sizes[1] / 2;
    int Nn = in_sizes[0] / D;
    int M  = Nn * D;
    const int* src = ei;
    const int* dst = ei + E;
    int L = Nn * R;
    int nb = (L + 255) / 256;

    cudaFuncSetAttribute(rgcn_hmma, cudaFuncAttributeMaxDynamicSharedMemorySize, SMEM_TOTAL);

    void *pCnt, *pStats, *pPool, *pGcnt;
    cudaGetSymbolAddress(&pCnt, g_cnt);
    cudaGetSymbolAddress(&pStats, g_lnstats);
    cudaGetSymbolAddress(&pPool, g_pool);
    cudaGetSymbolAddress(&pGcnt, g_gcnt);
    double* pst = (double*)pStats;

    cudaMemsetAsync(pCnt, 0, (size_t)NMAX * R * sizeof(int));
    count_kernel<<<(E + 255) / 256, 256>>>(dst, et, E);
    scan_atomic<<<nb, 256>>>(L);
    place_kernel<<<(E + 255) / 256, 256>>>(src, dst, et, E);

    const float* cur = x;
    float* bufs[2];
    cudaGetSymbolAddress((void**)&bufs[0], g_X0);
    cudaGetSymbolAddress((void**)&bufs[1], g_X1);

    for (int l = 0; l < 3; l++) {
        const double* sp = (l > 0) ? (pst + (l - 1) * 2) : nullptr;
        const float* pw = (l > 0) ? (ln_w + (l - 1) * D) : nullptr;
        const float* pb = (l > 0) ? (ln_b + (l - 1) * D) : nullptr;
        aggregate<<<NMAX, 256>>>(cur, pw, pb, sp, M, Nn);
        xconvert<<<NMAX * 32 / 256, 256>>>(cur, pw, pb, sp, M, Nn);
        prep_B<<<dim3(NST, D / 32), dim3(32, 8)>>>(
            W_rel + (size_t)l * R * D * D, W_root + (size_t)l * D * D);
        float* nxt = bufs[l & 1];
        double* so = (l < 2) ? (pst + l * 2) : nullptr;
        rgcn_hmma<<<NBLK, 256, SMEM_TOTAL>>>(
            cur, b_conv + l * D, nxt, Nn, pw, pb, sp, so, M);
        cur = nxt;
    }

    cudaMemsetAsync(pPool, 0, NG * D * sizeof(float));
    cudaMemsetAsync(pGcnt, 0, NG * sizeof(int));
    pool_cnt<<<(Nn + 255) / 256, 256>>>(batch, Nn);
    pool_sum<<<(Nn * (D / 4) + 255) / 256, 256>>>(cur, batch, Nn);
    head_kernel<<<NG, D>>>(W1, b1, W2, b2, W3, b3, (float*)d_out);
}

// round 11
// speedup vs baseline: 1.6121x; 1.6121x over previous
#include <cuda_runtime.h>
#include <cuda_bf16.h>
#include <math.h>
#include <stdint.h>

#define D    256
#define R    8
#define NG   64
#define NMAX 50176          // 392*128
#define NBLK 392
#define EPS  1e-5f
#define KTOT 2304           // (R+1)*D
#define NST  72             // KTOT / 32
#define BM   128
#define EMAX 1048576

// padded tile geometry (floats)
#define LDAf  36
#define ATILE (128 * LDAf)              // 4608 floats = 18432 B
#define BTILE (256 * LDAf)              // 9216 floats = 36864 B
#define OA    0
#define OB    18432
#define STG   55296                     // bytes per stage
#define NSTAGE 3
#define SMEM_TOTAL (NSTAGE * STG + 64)  // + mbarriers

// ---------------- static device scratch ----------------
__device__ float  g_A[(size_t)NBLK * NST * ATILE];   // tile-major, tf32-rounded
__device__ float  g_B[(size_t)NST * BTILE];          // tile-major, tf32-rounded
__device__ float  g_X0[(size_t)NMAX * D];
__device__ float  g_X1[(size_t)NMAX * D];
__device__ int    g_cnt[NMAX * R];
__device__ int    g_off[NMAX * R];
__device__ int    g_pos[NMAX * R];
__device__ int    g_cursor[1];
__device__ int    g_esrc[EMAX];
__device__ double g_lnstats[3][2];
__device__ float  g_pool[NG * D];
__device__ int    g_gcnt[NG];

// ---------------- helpers ----------------
__device__ __forceinline__ uint32_t smem_u32(const void* p) {
    return (uint32_t)__cvta_generic_to_shared((void*)p);
}
__device__ __forceinline__ void red_add_v4(float* addr, float4 v) {
    asm volatile("red.global.add.v4.f32 [%0], {%1,%2,%3,%4};"
                 :: "l"(addr), "f"(v.x), "f"(v.y), "f"(v.z), "f"(v.w) : "memory");
}
__device__ __forceinline__ void mma_tf32(float (&d)[4], const uint32_t (&a)[4],
                                         uint32_t b0, uint32_t b1) {
    asm volatile(
        "mma.sync.aligned.m16n8k8.row.col.f32.tf32.tf32.f32 "
        "{%0,%1,%2,%3}, {%4,%5,%6,%7}, {%8,%9}, {%0,%1,%2,%3};"
        : "+f"(d[0]), "+f"(d[1]), "+f"(d[2]), "+f"(d[3])
        : "r"(a[0]), "r"(a[1]), "r"(a[2]), "r"(a[3]), "r"(b0), "r"(b1));
}
__device__ __forceinline__ uint32_t f2tf(float f) {
    uint32_t u;
    asm("cvt.rna.tf32.f32 %0, %1;" : "=r"(u) : "f"(f));
    return u;
}
__device__ __forceinline__ void mbar_init(uint32_t mb, uint32_t cnt) {
    asm volatile("mbarrier.init.shared.b64 [%0], %1;" :: "r"(mb), "r"(cnt) : "memory");
}
__device__ __forceinline__ void mbar_expect_tx(uint32_t mb, uint32_t bytes) {
    asm volatile("mbarrier.arrive.expect_tx.shared.b64 _, [%0], %1;"
                 :: "r"(mb), "r"(bytes) : "memory");
}
__device__ __forceinline__ void mbar_wait(uint32_t mb, uint32_t ph) {
    asm volatile(
        "{\n\t.reg .pred P;\n\t"
        "LW%=:\n\t"
        "mbarrier.try_wait.parity.acquire.cta.shared::cta.b64 P, [%0], %1, 0x989680;\n\t"
        "@P bra LD%=;\n\t"
        "bra LW%=;\n\t"
        "LD%=:\n\t}"
        :: "r"(mb), "r"(ph) : "memory");
}
__device__ __forceinline__ void bulk_g2s(uint32_t dst, const void* src,
                                         uint32_t bytes, uint32_t mb) {
    asm volatile(
        "cp.async.bulk.shared::cta.global.mbarrier::complete_tx::bytes [%0], [%1], %2, [%3];"
        :: "r"(dst), "l"(src), "r"(bytes), "r"(mb) : "memory");
}
__device__ __forceinline__ void ln_params(const double* st, int M, float& mu, float& rs) {
    double m = st[0] / (double)M;
    double var = st[1] / (double)M - m * m;
    mu = (float)m;
    rs = 1.0f / ((float)sqrt(fmax(var, 0.0)) + EPS);
}

// ---------------- CSR build ----------------
__global__ void count_kernel(const int* __restrict__ dst, const int* __restrict__ et, int E) {
    int i = blockIdx.x * blockDim.x + threadIdx.x;
    if (blockIdx.x == 0) {
        if (threadIdx.x < 6) ((double*)g_lnstats)[threadIdx.x] = 0.0;
        if (threadIdx.x == 6) g_cursor[0] = 0;
    }
    if (i < E) atomicAdd(&g_cnt[dst[i] * R + et[i]], 1);
}

__global__ void scan_atomic(int L) {
    __shared__ int sh[256];
    __shared__ int sbase;
    int tid = threadIdx.x;
    int i = blockIdx.x * 256 + tid;
    int v = (i < L) ? g_cnt[i] : 0;
    sh[tid] = v; __syncthreads();
    #pragma unroll
    for (int o = 1; o < 256; o <<= 1) {
        int t = (tid >= o) ? sh[tid - o] : 0;
        __syncthreads();
        sh[tid] += t;
        __syncthreads();
    }
    if (tid == 255) sbase = atomicAdd(&g_cursor[0], sh[255]);
    __syncthreads();
    if (i < L) {
        int o = sbase + sh[tid] - v;
        g_off[i] = o;
        g_pos[i] = o;
    }
}

__global__ void place_kernel(const int* __restrict__ src, const int* __restrict__ dst,
                             const int* __restrict__ et, int E) {
    int e = blockIdx.x * blockDim.x + threadIdx.x;
    if (e < E) {
        int seg = dst[e] * R + et[e];
        int p = atomicAdd(&g_pos[seg], 1);
        g_esrc[p] = src[e];
    }
}

// ---------------- weight prep: transpose + tf32 round into tiled layout ----------------
__global__ void prep_B(const float* __restrict__ Wrel, const float* __restrict__ Wroot) {
    __shared__ float s[32][33];
    int k0 = blockIdx.x * 32, j0 = blockIdx.y * 32;
    int kt = blockIdx.x;
    for (int i = threadIdx.y; i < 32; i += 8) {
        int k = k0 + i;
        const float* row = (k < R * D) ? (Wrel + (size_t)k * D)
                                       : (Wroot + (size_t)(k - R * D) * D);
        s[i][threadIdx.x] = row[j0 + threadIdx.x];
    }
    __syncthreads();
    for (int i = threadIdx.y; i < 32; i += 8) {
        int j = j0 + i;
        uint32_t u = f2tf(s[threadIdx.x][i]);
        ((uint32_t*)g_B)[(size_t)kt * BTILE + j * LDAf + threadIdx.x] = u;
    }
}

// ---------------- aggregate: warp per (node, rel); lazy-LN; tiled tf32 out ----------------
__global__ __launch_bounds__(256) void aggregate(
    const float* __restrict__ x,
    const float* __restrict__ lnw, const float* __restrict__ lnb,
    const double* __restrict__ stats, int M, int Nn)
{
    int wid = threadIdx.x >> 5, lane = threadIdx.x & 31;
    int seg = blockIdx.x * 8 + wid;            // 0 .. NMAX*R-1
    int n = seg >> 3, r = seg & 7;
    int cnt = g_cnt[seg];
    int off = g_off[seg];
    float a[8] = {0, 0, 0, 0, 0, 0, 0, 0};
    if (cnt > 0) {
        int s = __ldg(&g_esrc[off]);
        for (int i = 1; i < cnt; i++) {
            int sn = __ldg(&g_esrc[off + i]);          // prefetch next index
            const float4* xp = (const float4*)(x + (size_t)s * D + lane * 8);
            float4 p0 = __ldg(xp), p1 = __ldg(xp + 1);
            a[0] += p0.x; a[1] += p0.y; a[2] += p0.z; a[3] += p0.w;
            a[4] += p1.x; a[5] += p1.y; a[6] += p1.z; a[7] += p1.w;
            s = sn;
        }
        const float4* xp = (const float4*)(x + (size_t)s * D + lane * 8);
        float4 p0 = __ldg(xp), p1 = __ldg(xp + 1);
        a[0] += p0.x; a[1] += p0.y; a[2] += p0.z; a[3] += p0.w;
        a[4] += p1.x; a[5] += p1.y; a[6] += p1.z; a[7] += p1.w;

        float sc = 1.0f / (float)cnt;
        #pragma unroll
        for (int q = 0; q < 8; q++) a[q] *= sc;
        if (stats != nullptr) {
            float mu, rs;
            ln_params(stats, M, mu, rs);
            int c0 = lane * 8;                         // column within relation block
            #pragma unroll
            for (int q = 0; q < 8; q++)
                a[q] = lnw[c0 + q] * ((a[q] - mu) * rs) + lnb[c0 + q];
        }
    }
    uint32_t w[8];
    #pragma unroll
    for (int q = 0; q < 8; q++) w[q] = f2tf(a[q]);
    // tiled write: kt = r*8 + (lane>>2), col-in-tile (lane&3)*8, row = n & 127
    int blk = n >> 7, row = n & 127;
    int kt = r * 8 + (lane >> 2);
    uint32_t* o = (uint32_t*)g_A + ((size_t)blk * NST + kt) * ATILE
                + row * LDAf + (lane & 3) * 8;
    *(uint4*)o       = make_uint4(w[0], w[1], w[2], w[3]);
    *(uint4*)(o + 4) = make_uint4(w[4], w[5], w[6], w[7]);
}

// ---------------- x -> tf32 into A tiles kt 64..71; lazy-LN ----------------
__global__ void xconvert(const float* __restrict__ x,
                         const float* __restrict__ lnw, const float* __restrict__ lnb,
                         const double* __restrict__ stats, int M, int Nn)
{
    int idx = blockIdx.x * blockDim.x + threadIdx.x;
    int n = idx >> 5, c8 = (idx & 31) * 8;
    if (n >= NMAX) return;
    float v[8] = {0, 0, 0, 0, 0, 0, 0, 0};
    if (n < Nn) {
        float4 p0 = *(const float4*)(x + (size_t)n * D + c8);
        float4 p1 = *(const float4*)(x + (size_t)n * D + c8 + 4);
        v[0] = p0.x; v[1] = p0.y; v[2] = p0.z; v[3] = p0.w;
        v[4] = p1.x; v[5] = p1.y; v[6] = p1.z; v[7] = p1.w;
        if (stats != nullptr) {
            float mu, rs;
            ln_params(stats, M, mu, rs);
            #pragma unroll
            for (int q = 0; q < 8; q++)
                v[q] = lnw[c8 + q] * ((v[q] - mu) * rs) + lnb[c8 + q];
        }
    }
    uint32_t w[8];
    #pragma unroll
    for (int q = 0; q < 8; q++) w[q] = f2tf(v[q]);
    int blk = n >> 7, row = n & 127;
    int kt = 64 + (c8 >> 5);
    uint32_t* o = (uint32_t*)g_A + ((size_t)blk * NST + kt) * ATILE
                + row * LDAf + (c8 & 31);
    *(uint4*)o       = make_uint4(w[0], w[1], w[2], w[3]);
    *(uint4*)(o + 4) = make_uint4(w[4], w[5], w[6], w[7]);
}

// ---------------- tf32 GEMM: bulk-DMA stages, 8 warps 64x64, 3-stage ----------------
__global__ __launch_bounds__(256) void rgcn_hmma(
    const float* __restrict__ Xcur,
    const float* __restrict__ bconv,
    float* __restrict__ Xnext, int Nn,
    const float* __restrict__ pw, const float* __restrict__ pb,
    const double* __restrict__ statsPrev,
    double* __restrict__ statsOut, int M)
{
    extern __shared__ char sm[];
    uint32_t sbase = smem_u32(sm);
    uint32_t mbb = sbase + NSTAGE * STG;
    int tid = threadIdx.x, lane = tid & 31, wid = tid >> 5;
    int wm = wid & 1, wn = wid >> 1;
    int row0 = blockIdx.x * BM;
    const float* gAblk = g_A + (size_t)blockIdx.x * NST * ATILE;

    if (tid == 0) {
        #pragma unroll
        for (int s = 0; s < NSTAGE; s++) mbar_init(mbb + s * 8, 1);
    }
    __syncthreads();
    if (tid == 0) {
        #pragma unroll
        for (int s = 0; s < NSTAGE; s++) {
            mbar_expect_tx(mbb + s * 8, STG);
            bulk_g2s(sbase + s * STG + OA, gAblk + (size_t)s * ATILE, 18432, mbb + s * 8);
            bulk_g2s(sbase + s * STG + OB, g_B + (size_t)s * BTILE, 36864, mbb + s * 8);
        }
    }

    float acc[4][8][4];
    #pragma unroll
    for (int i = 0; i < 4; i++)
        #pragma unroll
        for (int j = 0; j < 8; j++)
            #pragma unroll
            for (int q = 0; q < 4; q++) acc[i][j][q] = 0.f;

    int fr = lane >> 2, fc = lane & 3;

    #pragma unroll 1
    for (int kt = 0; kt < NST; kt++) {
        int b = kt % NSTAGE;
        mbar_wait(mbb + b * 8, (kt / 3) & 1);

        const uint32_t* As = (const uint32_t*)(sm + b * STG + OA);
        const uint32_t* Bs = (const uint32_t*)(sm + b * STG + OB);

        #pragma unroll
        for (int kc = 0; kc < 4; kc++) {
            uint32_t a[4][4];
            #pragma unroll
            for (int mi = 0; mi < 4; mi++) {
                const uint32_t* Ab = As + (wm * 64 + mi * 16 + fr) * LDAf + kc * 8 + fc;
                a[mi][0] = Ab[0];
                a[mi][1] = Ab[8 * LDAf];
                a[mi][2] = Ab[4];
                a[mi][3] = Ab[8 * LDAf + 4];
            }
            #pragma unroll
            for (int nj = 0; nj < 8; nj++) {
                const uint32_t* Bb = Bs + (wn * 64 + nj * 8 + fr) * LDAf + kc * 8 + fc;
                uint32_t b0 = Bb[0], b1 = Bb[4];
                #pragma unroll
                for (int mi = 0; mi < 4; mi++)
                    mma_tf32(acc[mi][nj], a[mi], b0, b1);
            }
        }
        __syncthreads();
        if (tid == 0 && kt + NSTAGE < NST) {
            mbar_expect_tx(mbb + b * 8, STG);
            bulk_g2s(sbase + b * STG + OA, gAblk + (size_t)(kt + NSTAGE) * ATILE,
                     18432, mbb + b * 8);
            bulk_g2s(sbase + b * STG + OB, g_B + (size_t)(kt + NSTAGE) * BTILE,
                     36864, mbb + b * 8);
        }
    }

    // ---- epilogue: bias + residual(affine) + relu + stats ----
    float mu = 0.f, rs = 0.f;
    bool ln = (statsPrev != nullptr);
    if (ln) ln_params(statsPrev, M, mu, rs);

    float ps = 0.f, pq = 0.f;
    #pragma unroll
    for (int mi = 0; mi < 4; mi++) {
        #pragma unroll
        for (int half = 0; half < 2; half++) {
            int n = row0 + wm * 64 + mi * 16 + fr + half * 8;
            if (n >= Nn) continue;
            #pragma unroll
            for (int nj = 0; nj < 8; nj++) {
                int col = wn * 64 + nj * 8 + fc * 2;
                float2 xv = *(const float2*)(Xcur + (size_t)n * D + col);
                float2 bv = *(const float2*)(bconv + col);
                if (ln) {
                    float2 wv = *(const float2*)(pw + col);
                    float2 bb = *(const float2*)(pb + col);
                    xv.x = wv.x * ((xv.x - mu) * rs) + bb.x;
                    xv.y = wv.y * ((xv.y - mu) * rs) + bb.y;
                }
                float2 o;
                o.x = fmaxf(acc[mi][nj][half * 2 + 0] + bv.x + xv.x, 0.f);
                o.y = fmaxf(acc[mi][nj][half * 2 + 1] + bv.y + xv.y, 0.f);
                *(float2*)(Xnext + (size_t)n * D + col) = o;
                ps += o.x + o.y;
                pq += o.x * o.x + o.y * o.y;
            }
        }
    }
    if (statsOut != nullptr) {
        #pragma unroll
        for (int o = 16; o > 0; o >>= 1) {
            ps += __shfl_down_sync(0xffffffffu, ps, o);
            pq += __shfl_down_sync(0xffffffffu, pq, o);
        }
        if (lane == 0) {
            atomicAdd(&statsOut[0], (double)ps);
            atomicAdd(&statsOut[1], (double)pq);
        }
    }
}

// ---------------- global mean pool + head ----------------
__global__ void pool_cnt(const int* __restrict__ batch, int Nn) {
    int i = blockIdx.x * blockDim.x + threadIdx.x;
    if (i < Nn) atomicAdd(&g_gcnt[batch[i]], 1);
}
__global__ void pool_sum(const float* __restrict__ X, const int* __restrict__ batch, int Nn) {
    int idx = blockIdx.x * blockDim.x + threadIdx.x;
    if (idx >= Nn * (D / 4)) return;
    int n = idx >> 6, c = idx & 63;
    float4 v = ((const float4*)X)[(size_t)n * (D / 4) + c];
    red_add_v4(g_pool + batch[n] * D + c * 4, v);
}
__global__ void head_kernel(const float* __restrict__ W1, const float* __restrict__ b1,
                            const float* __restrict__ W2, const float* __restrict__ b2,
                            const float* __restrict__ W3, const float* __restrict__ b3,
                            float* __restrict__ out) {
    __shared__ float g[D], h1[D], h2[D];
    int bg = blockIdx.x, j = threadIdx.x;
    float c = fmaxf((float)g_gcnt[bg], 1.f);
    g[j] = g_pool[bg * D + j] / c;
    __syncthreads();
    float acc = b1[j];
    for (int k = 0; k < D; k++) acc = fmaf(g[k], W1[k * D + j], acc);
    h1[j] = fmaxf(acc, 0.f);
    __syncthreads();
    acc = b2[j];
    for (int k = 0; k < D; k++) acc = fmaf(h1[k], W2[k * D + j], acc);
    h2[j] = fmaxf(acc, 0.f);
    __syncthreads();
    if (j < 4) {
        acc = b3[j];
        for (int k = 0; k < D; k++) acc = fmaf(h2[k], W3[k * 4 + j], acc);
        out[bg * 4 + j] = acc;
    }
}

// ---------------- launch ----------------
extern "C" void kernel_launch(void* const* d_in, const int* in_sizes, int n_in,
                              void* d_out, int out_size) {
    const float* x      = (const float*)d_in[0];
    const int*   ei     = (const int*)d_in[1];
    const int*   et     = (const int*)d_in[2];
    const int*   batch  = (const int*)d_in[3];
    const float* W_rel  = (const float*)d_in[4];
    const float* W_root = (const float*)d_in[5];
    const float* b_conv = (const float*)d_in[6];
    const float* ln_w   = (const float*)d_in[7];
    const float* ln_b   = (const float*)d_in[8];
    const float* W1 = (const float*)d_in[9];
    const float* b1 = (const float*)d_in[10];
    const float* W2 = (const float*)d_in[11];
    const float* b2 = (const float*)d_in[12];
    const float* W3 = (const float*)d_in[13];
    const float* b3 = (const float*)d_in[14];

    int E  = in_sizes[1] / 2;
    int Nn = in_sizes[0] / D;
    int M  = Nn * D;
    const int* src = ei;
    const int* dst = ei + E;
    int L = Nn * R;
    int nb = (L + 255) / 256;

    cudaFuncSetAttribute(rgcn_hmma, cudaFuncAttributeMaxDynamicSharedMemorySize, SMEM_TOTAL);

    void *pCnt, *pStats, *pPool, *pGcnt;
    cudaGetSymbolAddress(&pCnt, g_cnt);
    cudaGetSymbolAddress(&pStats, g_lnstats);
    cudaGetSymbolAddress(&pPool, g_pool);
    cudaGetSymbolAddress(&pGcnt, g_gcnt);
    double* pst = (double*)pStats;

    cudaMemsetAsync(pCnt, 0, (size_t)NMAX * R * sizeof(int));
    count_kernel<<<(E + 255) / 256, 256>>>(dst, et, E);
    scan_atomic<<<nb, 256>>>(L);
    place_kernel<<<(E + 255) / 256, 256>>>(src, dst, et, E);

    const float* cur = x;
    float* bufs[2];
    cudaGetSymbolAddress((void**)&bufs[0], g_X0);
    cudaGetSymbolAddress((void**)&bufs[1], g_X1);

    for (int l = 0; l < 3; l++) {
        const double* sp = (l > 0) ? (pst + (l - 1) * 2) : nullptr;
        const float* pw = (l > 0) ? (ln_w + (l - 1) * D) : nullptr;
        const float* pb = (l > 0) ? (ln_b + (l - 1) * D) : nullptr;
        aggregate<<<NMAX, 256>>>(cur, pw, pb, sp, M, Nn);
        xconvert<<<NMAX * 32 / 256, 256>>>(cur, pw, pb, sp, M, Nn);
        prep_B<<<dim3(NST, D / 32), dim3(32, 8)>>>(
            W_rel + (size_t)l * R * D * D, W_root + (size_t)l * D * D);
        float* nxt = bufs[l & 1];
        double* so = (l < 2) ? (pst + l * 2) : nullptr;
        rgcn_hmma<<<NBLK, 256, SMEM_TOTAL>>>(
            cur, b_conv + l * D, nxt, Nn, pw, pb, sp, so, M);
        cur = nxt;
    }

    cudaMemsetAsync(pPool, 0, NG * D * sizeof(float));
    cudaMemsetAsync(pGcnt, 0, NG * sizeof(int));
    pool_cnt<<<(Nn + 255) / 256, 256>>>(batch, Nn);
    pool_sum<<<(Nn * (D / 4) + 255) / 256, 256>>>(cur, batch, Nn);
    head_kernel<<<NG, D>>>(W1, b1, W2, b2, W3, b3, (float*)d_out);
}

// round 12
// speedup vs baseline: 1.6270x; 1.0093x over previous
#include <cuda_runtime.h>
#include <cuda_bf16.h>
#include <math.h>
#include <stdint.h>

#define D    256
#define R    8
#define NG   64
#define NMAX 50176          // 392*128
#define NBLK 392
#define EPS  1e-5f
#define KTOT 2304           // (R+1)*D
#define NST  72             // KTOT / 32
#define BM   128
#define EMAX 1048576

// padded tile geometry (floats)
#define LDAf  36
#define ATILE (128 * LDAf)              // 18432 B
#define BTILE (256 * LDAf)              // 36864 B
#define OA    0
#define OB    18432
#define STG   55296
#define NSTAGE 3
#define SMEM_TOTAL (NSTAGE * STG + 64)

// ---------------- static device scratch ----------------
__device__ float  g_B[(size_t)NST * BTILE];          // tile-major, tf32-rounded
__device__ float  g_X0[(size_t)NMAX * D];
__device__ float  g_X1[(size_t)NMAX * D];
__device__ int    g_cnt[NMAX * R];
__device__ int    g_off[NMAX * R];
__device__ int    g_pos[NMAX * R];
__device__ int    g_cursor[1];
__device__ int    g_esrc[EMAX];
__device__ double g_lnstats[3][2];
__device__ float  g_pool[NG * D];
__device__ int    g_gcnt[NG];

// ---------------- helpers ----------------
__device__ __forceinline__ uint32_t smem_u32(const void* p) {
    return (uint32_t)__cvta_generic_to_shared((void*)p);
}
__device__ __forceinline__ void red_add_v4(float* addr, float4 v) {
    asm volatile("red.global.add.v4.f32 [%0], {%1,%2,%3,%4};"
                 :: "l"(addr), "f"(v.x), "f"(v.y), "f"(v.z), "f"(v.w) : "memory");
}
__device__ __forceinline__ void mma_tf32(float (&d)[4], const uint32_t (&a)[4],
                                         uint32_t b0, uint32_t b1) {
    asm volatile(
        "mma.sync.aligned.m16n8k8.row.col.f32.tf32.tf32.f32 "
        "{%0,%1,%2,%3}, {%4,%5,%6,%7}, {%8,%9}, {%0,%1,%2,%3};"
        : "+f"(d[0]), "+f"(d[1]), "+f"(d[2]), "+f"(d[3])
        : "r"(a[0]), "r"(a[1]), "r"(a[2]), "r"(a[3]), "r"(b0), "r"(b1));
}
__device__ __forceinline__ uint32_t f2tf(float f) {
    uint32_t u;
    asm("cvt.rna.tf32.f32 %0, %1;" : "=r"(u) : "f"(f));
    return u;
}
__device__ __forceinline__ void mbar_init(uint32_t mb, uint32_t cnt) {
    asm volatile("mbarrier.init.shared.b64 [%0], %1;" :: "r"(mb), "r"(cnt) : "memory");
}
__device__ __forceinline__ void mbar_expect_tx(uint32_t mb, uint32_t bytes) {
    asm volatile("mbarrier.arrive.expect_tx.shared.b64 _, [%0], %1;"
                 :: "r"(mb), "r"(bytes) : "memory");
}
__device__ __forceinline__ void mbar_wait(uint32_t mb, uint32_t ph) {
    asm volatile(
        "{\n\t.reg .pred P;\n\t"
        "LW%=:\n\t"
        "mbarrier.try_wait.parity.acquire.cta.shared::cta.b64 P, [%0], %1, 0x989680;\n\t"
        "@P bra LD%=;\n\t"
        "bra LW%=;\n\t"
        "LD%=:\n\t}"
        :: "r"(mb), "r"(ph) : "memory");
}
__device__ __forceinline__ void bulk_g2s(uint32_t dst, const void* src,
                                         uint32_t bytes, uint32_t mb) {
    asm volatile(
        "cp.async.bulk.shared::cta.global.mbarrier::complete_tx::bytes [%0], [%1], %2, [%3];"
        :: "r"(dst), "l"(src), "r"(bytes), "r"(mb) : "memory");
}
__device__ __forceinline__ void ln_params(const double* st, int M, float& mu, float& rs) {
    double m = st[0] / (double)M;
    double var = st[1] / (double)M - m * m;
    mu = (float)m;
    rs = 1.0f / ((float)sqrt(fmax(var, 0.0)) + EPS);
}

// ---------------- CSR build ----------------
__global__ void count_kernel(const int* __restrict__ dst, const int* __restrict__ et, int E) {
    int i = blockIdx.x * blockDim.x + threadIdx.x;
    if (blockIdx.x == 0) {
        if (threadIdx.x < 6) ((double*)g_lnstats)[threadIdx.x] = 0.0;
        if (threadIdx.x == 6) g_cursor[0] = 0;
    }
    if (i < E) atomicAdd(&g_cnt[dst[i] * R + et[i]], 1);
}

__global__ void scan_atomic(int L) {
    __shared__ int sh[256];
    __shared__ int sbase;
    int tid = threadIdx.x;
    int i = blockIdx.x * 256 + tid;
    int v = (i < L) ? g_cnt[i] : 0;
    sh[tid] = v; __syncthreads();
    #pragma unroll
    for (int o = 1; o < 256; o <<= 1) {
        int t = (tid >= o) ? sh[tid - o] : 0;
        __syncthreads();
        sh[tid] += t;
        __syncthreads();
    }
    if (tid == 255) sbase = atomicAdd(&g_cursor[0], sh[255]);
    __syncthreads();
    if (i < L) {
        int o = sbase + sh[tid] - v;
        g_off[i] = o;
        g_pos[i] = o;
    }
}

__global__ void place_kernel(const int* __restrict__ src, const int* __restrict__ dst,
                             const int* __restrict__ et, int E) {
    int e = blockIdx.x * blockDim.x + threadIdx.x;
    if (e < E) {
        int seg = dst[e] * R + et[e];
        int p = atomicAdd(&g_pos[seg], 1);
        g_esrc[p] = src[e];
    }
}

// ---------------- weight prep: transpose + tf32 round into tiled layout ----------------
__global__ void prep_B(const float* __restrict__ Wrel, const float* __restrict__ Wroot) {
    __shared__ float s[32][33];
    int k0 = blockIdx.x * 32, j0 = blockIdx.y * 32;
    int kt = blockIdx.x;
    for (int i = threadIdx.y; i < 32; i += 8) {
        int k = k0 + i;
        const float* row = (k < R * D) ? (Wrel + (size_t)k * D)
                                       : (Wroot + (size_t)(k - R * D) * D);
        s[i][threadIdx.x] = row[j0 + threadIdx.x];
    }
    __syncthreads();
    for (int i = threadIdx.y; i < 32; i += 8) {
        int j = j0 + i;
        uint32_t u = f2tf(s[threadIdx.x][i]);
        ((uint32_t*)g_B)[(size_t)kt * BTILE + j * LDAf + threadIdx.x] = u;
    }
}

// ---------------- fused GEMM: in-kernel aggregation + tf32 HMMA ----------------
// Per CTA: 128 nodes. A stage filled in-kernel from CSR gather; B via bulk DMA.
__global__ __launch_bounds__(256) void rgcn_fused(
    const float* __restrict__ Xcur,
    const float* __restrict__ bconv,
    float* __restrict__ Xnext, int Nn,
    const float* __restrict__ pw, const float* __restrict__ pb,
    const double* __restrict__ statsPrev,
    double* __restrict__ statsOut, int M)
{
    extern __shared__ char sm[];
    uint32_t sbase = smem_u32(sm);
    uint32_t mbb = sbase + NSTAGE * STG;
    int tid = threadIdx.x, lane = tid & 31, wid = tid >> 5;
    int wm = wid & 1, wn = wid >> 1;
    int row0 = blockIdx.x * BM;

    float mu = 0.f, rs = 0.f;
    bool ln = (statsPrev != nullptr);
    if (ln) ln_params(statsPrev, M, mu, rs);

    // ---- A producer: thread t fills node n=t>>1, 16 cols (half h=t&1) of k-tile kt ----
    int fn = tid >> 1, fh = tid & 1;
    int fnode = row0 + fn;
    bool fvalid = fnode < Nn;
    float* fdstBase = (float*)sm;   // offset per stage added at call

    auto fill_A = [&](int kt, int stg) {
        float v[16];
        #pragma unroll
        for (int q = 0; q < 16; q++) v[q] = 0.f;
        int cbase;
        if (kt < 64) {
            int r = kt >> 3, c = kt & 7;
            cbase = c * 32 + fh * 16;
            if (fvalid) {
                int seg = fnode * R + r;
                int cnt = g_cnt[seg];
                int off = g_off[seg];
                if (cnt > 0) {
                    for (int i = 0; i < cnt; i++) {
                        int s = __ldg(&g_esrc[off + i]);
                        const float4* xp = (const float4*)(Xcur + (size_t)s * D + cbase);
                        float4 p0 = __ldg(xp), p1 = __ldg(xp + 1);
                        float4 p2 = __ldg(xp + 2), p3 = __ldg(xp + 3);
                        v[0] += p0.x;  v[1] += p0.y;  v[2] += p0.z;  v[3] += p0.w;
                        v[4] += p1.x;  v[5] += p1.y;  v[6] += p1.z;  v[7] += p1.w;
                        v[8] += p2.x;  v[9] += p2.y;  v[10] += p2.z; v[11] += p2.w;
                        v[12] += p3.x; v[13] += p3.y; v[14] += p3.z; v[15] += p3.w;
                    }
                    float sc = 1.0f / (float)cnt;
                    #pragma unroll
                    for (int q = 0; q < 16; q++) v[q] *= sc;
                    if (ln) {
                        #pragma unroll
                        for (int q = 0; q < 16; q++)
                            v[q] = pw[cbase + q] * ((v[q] - mu) * rs) + pb[cbase + q];
                    }
                }
            }
        } else {
            int c = kt - 64;
            cbase = c * 32 + fh * 16;
            if (fvalid) {
                const float4* xp = (const float4*)(Xcur + (size_t)fnode * D + cbase);
                float4 p0 = *xp, p1 = xp[1], p2 = xp[2], p3 = xp[3];
                v[0] = p0.x;  v[1] = p0.y;  v[2] = p0.z;  v[3] = p0.w;
                v[4] = p1.x;  v[5] = p1.y;  v[6] = p1.z;  v[7] = p1.w;
                v[8] = p2.x;  v[9] = p2.y;  v[10] = p2.z; v[11] = p2.w;
                v[12] = p3.x; v[13] = p3.y; v[14] = p3.z; v[15] = p3.w;
                if (ln) {
                    #pragma unroll
                    for (int q = 0; q < 16; q++)
                        v[q] = pw[cbase + q] * ((v[q] - mu) * rs) + pb[cbase + q];
                }
            }
        }
        uint32_t w[16];
        #pragma unroll
        for (int q = 0; q < 16; q++) w[q] = f2tf(v[q]);
        uint32_t* dst = (uint32_t*)(fdstBase + (size_t)stg * (STG / 4)) + fn * LDAf + fh * 16;
        *(uint4*)dst       = make_uint4(w[0], w[1], w[2], w[3]);
        *(uint4*)(dst + 4) = make_uint4(w[4], w[5], w[6], w[7]);
        *(uint4*)(dst + 8) = make_uint4(w[8], w[9], w[10], w[11]);
        *(uint4*)(dst + 12)= make_uint4(w[12], w[13], w[14], w[15]);
    };

    if (tid == 0) {
        #pragma unroll
        for (int s = 0; s < NSTAGE; s++) mbar_init(mbb + s * 8, 1);
    }
    __syncthreads();
    if (tid == 0) {
        #pragma unroll
        for (int s = 0; s < NSTAGE; s++) {
            mbar_expect_tx(mbb + s * 8, 36864);
            bulk_g2s(sbase + s * STG + OB, g_B + (size_t)s * BTILE, 36864, mbb + s * 8);
        }
    }
    fill_A(0, 0);
    fill_A(1, 1);
    __syncthreads();

    float acc[4][8][4];
    #pragma unroll
    for (int i = 0; i < 4; i++)
        #pragma unroll
        for (int j = 0; j < 8; j++)
            #pragma unroll
            for (int q = 0; q < 4; q++) acc[i][j][q] = 0.f;

    int fr = lane >> 2, fc = lane & 3;

    #pragma unroll 1
    for (int kt = 0; kt < NST; kt++) {
        int b = kt % NSTAGE;
        mbar_wait(mbb + b * 8, (kt / 3) & 1);

        const uint32_t* As = (const uint32_t*)(sm + b * STG + OA);
        const uint32_t* Bs = (const uint32_t*)(sm + b * STG + OB);

        #pragma unroll
        for (int kc = 0; kc < 4; kc++) {
            uint32_t a[4][4];
            #pragma unroll
            for (int mi = 0; mi < 4; mi++) {
                const uint32_t* Ab = As + (wm * 64 + mi * 16 + fr) * LDAf + kc * 8 + fc;
                a[mi][0] = Ab[0];
                a[mi][1] = Ab[8 * LDAf];
                a[mi][2] = Ab[4];
                a[mi][3] = Ab[8 * LDAf + 4];
            }
            #pragma unroll
            for (int nj = 0; nj < 8; nj++) {
                const uint32_t* Bb = Bs + (wn * 64 + nj * 8 + fr) * LDAf + kc * 8 + fc;
                uint32_t b0 = Bb[0], b1 = Bb[4];
                #pragma unroll
                for (int mi = 0; mi < 4; mi++)
                    mma_tf32(acc[mi][nj], a[mi], b0, b1);
            }
        }
        if (kt + 2 < NST) fill_A(kt + 2, (kt + 2) % NSTAGE);
        __syncthreads();
        if (tid == 0 && kt + NSTAGE < NST) {
            mbar_expect_tx(mbb + b * 8, 36864);
            bulk_g2s(sbase + b * STG + OB, g_B + (size_t)(kt + NSTAGE) * BTILE,
                     36864, mbb + b * 8);
        }
    }

    // ---- epilogue: bias + residual(affine) + relu + stats ----
    float ps = 0.f, pq = 0.f;
    #pragma unroll
    for (int mi = 0; mi < 4; mi++) {
        #pragma unroll
        for (int half = 0; half < 2; half++) {
            int n = row0 + wm * 64 + mi * 16 + fr + half * 8;
            if (n >= Nn) continue;
            #pragma unroll
            for (int nj = 0; nj < 8; nj++) {
                int col = wn * 64 + nj * 8 + fc * 2;
                float2 xv = *(const float2*)(Xcur + (size_t)n * D + col);
                float2 bv = *(const float2*)(bconv + col);
                if (ln) {
                    float2 wv = *(const float2*)(pw + col);
                    float2 bb = *(const float2*)(pb + col);
                    xv.x = wv.x * ((xv.x - mu) * rs) + bb.x;
                    xv.y = wv.y * ((xv.y - mu) * rs) + bb.y;
                }
                float2 o;
                o.x = fmaxf(acc[mi][nj][half * 2 + 0] + bv.x + xv.x, 0.f);
                o.y = fmaxf(acc[mi][nj][half * 2 + 1] + bv.y + xv.y, 0.f);
                *(float2*)(Xnext + (size_t)n * D + col) = o;
                ps += o.x + o.y;
                pq += o.x * o.x + o.y * o.y;
            }
        }
    }
    if (statsOut != nullptr) {
        #pragma unroll
        for (int o = 16; o > 0; o >>= 1) {
            ps += __shfl_down_sync(0xffffffffu, ps, o);
            pq += __shfl_down_sync(0xffffffffu, pq, o);
        }
        if (lane == 0) {
            atomicAdd(&statsOut[0], (double)ps);
            atomicAdd(&statsOut[1], (double)pq);
        }
    }
}

// ---------------- global mean pool + head ----------------
__global__ void pool_cnt(const int* __restrict__ batch, int Nn) {
    int i = blockIdx.x * blockDim.x + threadIdx.x;
    if (i < Nn) atomicAdd(&g_gcnt[batch[i]], 1);
}
__global__ void pool_sum(const float* __restrict__ X, const int* __restrict__ batch, int Nn) {
    int idx = blockIdx.x * blockDim.x + threadIdx.x;
    if (idx >= Nn * (D / 4)) return;
    int n = idx >> 6, c = idx & 63;
    float4 v = ((const float4*)X)[(size_t)n * (D / 4) + c];
    red_add_v4(g_pool + batch[n] * D + c * 4, v);
}
__global__ void head_kernel(const float* __restrict__ W1, const float* __restrict__ b1,
                            const float* __restrict__ W2, const float* __restrict__ b2,
                            const float* __restrict__ W3, const float* __restrict__ b3,
                            float* __restrict__ out) {
    __shared__ float g[D], h1[D], h2[D];
    int bg = blockIdx.x, j = threadIdx.x;
    float c = fmaxf((float)g_gcnt[bg], 1.f);
    g[j] = g_pool[bg * D + j] / c;
    __syncthreads();
    float acc = b1[j];
    for (int k = 0; k < D; k++) acc = fmaf(g[k], W1[k * D + j], acc);
    h1[j] = fmaxf(acc, 0.f);
    __syncthreads();
    acc = b2[j];
    for (int k = 0; k < D; k++) acc = fmaf(h1[k], W2[k * D + j], acc);
    h2[j] = fmaxf(acc, 0.f);
    __syncthreads();
    if (j < 4) {
        acc = b3[j];
        for (int k = 0; k < D; k++) acc = fmaf(h2[k], W3[k * 4 + j], acc);
        out[bg * 4 + j] = acc;
    }
}

// ---------------- launch ----------------
extern "C" void kernel_launch(void* const* d_in, const int* in_sizes, int n_in,
                              void* d_out, int out_size) {
    const float* x      = (const float*)d_in[0];
    const int*   ei     = (const int*)d_in[1];
    const int*   et     = (const int*)d_in[2];
    const int*   batch  = (const int*)d_in[3];
    const float* W_rel  = (const float*)d_in[4];
    const float* W_root = (const float*)d_in[5];
    const float* b_conv = (const float*)d_in[6];
    const float* ln_w   = (const float*)d_in[7];
    const float* ln_b   = (const float*)d_in[8];
    const float* W1 = (const float*)d_in[9];
    const float* b1 = (const float*)d_in[10];
    const float* W2 = (const float*)d_in[11];
    const float* b2 = (const float*)d_in[12];
    const float* W3 = (const float*)d_in[13];
    const float* b3 = (const float*)d_in[14];

    int E  = in_sizes[1] / 2;
    int Nn = in_sizes[0] / D;
    int M  = Nn * D;
    const int* src = ei;
    const int* dst = ei + E;
    int L = Nn * R;
    int nb = (L + 255) / 256;

    cudaFuncSetAttribute(rgcn_fused, cudaFuncAttributeMaxDynamicSharedMemorySize, SMEM_TOTAL);

    void *pCnt, *pStats, *pPool, *pGcnt;
    cudaGetSymbolAddress(&pCnt, g_cnt);
    cudaGetSymbolAddress(&pStats, g_lnstats);
    cudaGetSymbolAddress(&pPool, g_pool);
    cudaGetSymbolAddress(&pGcnt, g_gcnt);
    double* pst = (double*)pStats;

    cudaMemsetAsync(pCnt, 0, (size_t)NMAX * R * sizeof(int));
    count_kernel<<<(E + 255) / 256, 256>>>(dst, et, E);
    scan_atomic<<<nb, 256>>>(L);
    place_kernel<<<(E + 255) / 256, 256>>>(src, dst, et, E);

    const float* cur = x;
    float* bufs[2];
    cudaGetSymbolAddress((void**)&bufs[0], g_X0);
    cudaGetSymbolAddress((void**)&bufs[1], g_X1);

    for (int l = 0; l < 3; l++) {
        const double* sp = (l > 0) ? (pst + (l - 1) * 2) : nullptr;
        const float* pw = (l > 0) ? (ln_w + (l - 1) * D) : nullptr;
        const float* pb = (l > 0) ? (ln_b + (l - 1) * D) : nullptr;
        prep_B<<<dim3(NST, D / 32), dim3(32, 8)>>>(
            W_rel + (size_t)l * R * D * D, W_root + (size_t)l * D * D);
        float* nxt = bufs[l & 1];
        double* so = (l < 2) ? (pst + l * 2) : nullptr;
        rgcn_fused<<<NBLK, 256, SMEM_TOTAL>>>(
            cur, b_conv + l * D, nxt, Nn, pw, pb, sp, so, M);
        cur = nxt;
    }

    cudaMemsetAsync(pPool, 0, NG * D * sizeof(float));
    cudaMemsetAsync(pGcnt, 0, NG * sizeof(int));
    pool_cnt<<<(Nn + 255) / 256, 256>>>(batch, Nn);
    pool_sum<<<(Nn * (D / 4) + 255) / 256, 256>>>(cur, batch, Nn);
    head_kernel<<<NG, D>>>(W1, b1, W2, b2, W3, b3, (float*)d_out);
}

// round 13
// speedup vs baseline: 1.7897x; 1.1000x over previous
#include <cuda_runtime.h>
#include <cuda_bf16.h>
#include <math.h>
#include <stdint.h>

#define D    256
#define R    8
#define NG   64
#define NMAX 50176          // 392*128
#define NBLK 392
#define EPS  1e-5f
#define KTOT 2304           // (R+1)*D
#define NST  72             // KTOT / 32
#define BM   128
#define EMAX 1048576

// padded tile geometry (floats)
#define LDAf  36
#define ATILE (128 * LDAf)              // 18432 B
#define BTILE (256 * LDAf)              // 36864 B
#define OA    0
#define OB    18432
#define STG   55296
#define NSTAGE 3
#define SMEM_TOTAL (NSTAGE * STG + 128)

// ---------------- static device scratch ----------------
__device__ float  g_B[(size_t)NST * BTILE];          // tile-major, tf32-rounded
__device__ float  g_X0[(size_t)NMAX * D];
__device__ float  g_X1[(size_t)NMAX * D];
__device__ int    g_cnt[NMAX * R];
__device__ int    g_off[NMAX * R];
__device__ int    g_pos[NMAX * R];
__device__ int    g_cursor[1];
__device__ int    g_esrc[EMAX];
__device__ double g_lnstats[3][2];
__device__ float  g_pool[NG * D];
__device__ int    g_gcnt[NG];

// ---------------- helpers ----------------
__device__ __forceinline__ uint32_t smem_u32(const void* p) {
    return (uint32_t)__cvta_generic_to_shared((void*)p);
}
__device__ __forceinline__ void red_add_v4(float* addr, float4 v) {
    asm volatile("red.global.add.v4.f32 [%0], {%1,%2,%3,%4};"
                 :: "l"(addr), "f"(v.x), "f"(v.y), "f"(v.z), "f"(v.w) : "memory");
}
__device__ __forceinline__ void mma_tf32(float (&d)[4], const uint32_t (&a)[4],
                                         uint32_t b0, uint32_t b1) {
    asm volatile(
        "mma.sync.aligned.m16n8k8.row.col.f32.tf32.tf32.f32 "
        "{%0,%1,%2,%3}, {%4,%5,%6,%7}, {%8,%9}, {%0,%1,%2,%3};"
        : "+f"(d[0]), "+f"(d[1]), "+f"(d[2]), "+f"(d[3])
        : "r"(a[0]), "r"(a[1]), "r"(a[2]), "r"(a[3]), "r"(b0), "r"(b1));
}
__device__ __forceinline__ uint32_t f2tf(float f) {
    uint32_t u;
    asm("cvt.rna.tf32.f32 %0, %1;" : "=r"(u) : "f"(f));
    return u;
}
__device__ __forceinline__ void mbar_init(uint32_t mb, uint32_t cnt) {
    asm volatile("mbarrier.init.shared.b64 [%0], %1;" :: "r"(mb), "r"(cnt) : "memory");
}
__device__ __forceinline__ void mbar_arrive(uint32_t mb) {
    asm volatile("mbarrier.arrive.shared.b64 _, [%0];" :: "r"(mb) : "memory");
}
__device__ __forceinline__ void mbar_expect_tx(uint32_t mb, uint32_t bytes) {
    asm volatile("mbarrier.arrive.expect_tx.shared.b64 _, [%0], %1;"
                 :: "r"(mb), "r"(bytes) : "memory");
}
__device__ __forceinline__ void mbar_wait(uint32_t mb, uint32_t ph) {
    asm volatile(
        "{\n\t.reg .pred P;\n\t"
        "LW%=:\n\t"
        "mbarrier.try_wait.parity.acquire.cta.shared::cta.b64 P, [%0], %1, 0x989680;\n\t"
        "@P bra LD%=;\n\t"
        "bra LW%=;\n\t"
        "LD%=:\n\t}"
        :: "r"(mb), "r"(ph) : "memory");
}
__device__ __forceinline__ void bulk_g2s(uint32_t dst, const void* src,
                                         uint32_t bytes, uint32_t mb) {
    asm volatile(
        "cp.async.bulk.shared::cta.global.mbarrier::complete_tx::bytes [%0], [%1], %2, [%3];"
        :: "r"(dst), "l"(src), "r"(bytes), "r"(mb) : "memory");
}
__device__ __forceinline__ void ln_params(const double* st, int M, float& mu, float& rs) {
    double m = st[0] / (double)M;
    double var = st[1] / (double)M - m * m;
    mu = (float)m;
    rs = 1.0f / ((float)sqrt(fmax(var, 0.0)) + EPS);
}

// ---------------- CSR build ----------------
__global__ void count_kernel(const int* __restrict__ dst, const int* __restrict__ et, int E) {
    int i = blockIdx.x * blockDim.x + threadIdx.x;
    if (blockIdx.x == 0) {
        if (threadIdx.x < 6) ((double*)g_lnstats)[threadIdx.x] = 0.0;
        if (threadIdx.x == 6) g_cursor[0] = 0;
    }
    if (i < E) atomicAdd(&g_cnt[dst[i] * R + et[i]], 1);
}

__global__ void scan_atomic(int L) {
    __shared__ int sh[256];
    __shared__ int sbase;
    int tid = threadIdx.x;
    int i = blockIdx.x * 256 + tid;
    int v = (i < L) ? g_cnt[i] : 0;
    sh[tid] = v; __syncthreads();
    #pragma unroll
    for (int o = 1; o < 256; o <<= 1) {
        int t = (tid >= o) ? sh[tid - o] : 0;
        __syncthreads();
        sh[tid] += t;
        __syncthreads();
    }
    if (tid == 255) sbase = atomicAdd(&g_cursor[0], sh[255]);
    __syncthreads();
    if (i < L) {
        int o = sbase + sh[tid] - v;
        g_off[i] = o;
        g_pos[i] = o;
    }
}

__global__ void place_kernel(const int* __restrict__ src, const int* __restrict__ dst,
                             const int* __restrict__ et, int E) {
    int e = blockIdx.x * blockDim.x + threadIdx.x;
    if (e < E) {
        int seg = dst[e] * R + et[e];
        int p = atomicAdd(&g_pos[seg], 1);
        g_esrc[p] = src[e];
    }
}

// ---------------- weight prep ----------------
__global__ void prep_B(const float* __restrict__ Wrel, const float* __restrict__ Wroot) {
    __shared__ float s[32][33];
    int k0 = blockIdx.x * 32, j0 = blockIdx.y * 32;
    int kt = blockIdx.x;
    for (int i = threadIdx.y; i < 32; i += 8) {
        int k = k0 + i;
        const float* row = (k < R * D) ? (Wrel + (size_t)k * D)
                                       : (Wroot + (size_t)(k - R * D) * D);
        s[i][threadIdx.x] = row[j0 + threadIdx.x];
    }
    __syncthreads();
    for (int i = threadIdx.y; i < 32; i += 8) {
        int j = j0 + i;
        uint32_t u = f2tf(s[threadIdx.x][i]);
        ((uint32_t*)g_B)[(size_t)kt * BTILE + j * LDAf + threadIdx.x] = u;
    }
}

// ---------------- fused warp-specialized GEMM ----------------
// 384 threads: warps 0-7 consumers (MMA), warps 8-11 producers (A gather).
__global__ __launch_bounds__(384, 1) void rgcn_fused(
    const float* __restrict__ Xcur,
    const float* __restrict__ bconv,
    float* __restrict__ Xnext, int Nn,
    const float* __restrict__ pw, const float* __restrict__ pb,
    const double* __restrict__ statsPrev,
    double* __restrict__ statsOut, int M)
{
    extern __shared__ char sm[];
    uint32_t sbase = smem_u32(sm);
    uint32_t mb_bfull  = sbase + NSTAGE * STG;        // 3 x 8B
    uint32_t mb_afull  = mb_bfull + 24;               // 3 x 8B
    uint32_t mb_aempty = mb_afull + 24;               // 3 x 8B
    int tid = threadIdx.x, lane = tid & 31, wid = tid >> 5;
    int row0 = blockIdx.x * BM;

    float mu = 0.f, rs = 0.f;
    bool ln = (statsPrev != nullptr);
    if (ln) ln_params(statsPrev, M, mu, rs);

    if (tid == 0) {
        #pragma unroll
        for (int s = 0; s < NSTAGE; s++) {
            mbar_init(mb_bfull + s * 8, 1);
            mbar_init(mb_afull + s * 8, 128);
            mbar_init(mb_aempty + s * 8, 1);
        }
    }
    __syncthreads();
    if (tid == 0) {
        #pragma unroll
        for (int s = 0; s < NSTAGE; s++) {
            mbar_expect_tx(mb_bfull + s * 8, 36864);
            bulk_g2s(sbase + s * STG + OB, g_B + (size_t)s * BTILE, 36864, mb_bfull + s * 8);
        }
    }

    if (wid >= 8) {
        // ================= PRODUCER: 128 threads, one node each =================
        int fn = tid - 256;
        int fnode = row0 + fn;
        bool fvalid = fnode < Nn;
        #pragma unroll 1
        for (int kt = 0; kt < NST; kt++) {
            int s = kt % NSTAGE;
            if (kt >= NSTAGE)
                mbar_wait(mb_aempty + s * 8, ((kt / 3) + 1) & 1);
            float v[32];
            #pragma unroll
            for (int q = 0; q < 32; q++) v[q] = 0.f;
            int cbase = (kt < 64) ? ((kt & 7) * 32) : ((kt - 64) * 32);
            if (fvalid) {
                if (kt < 64) {
                    int seg = fnode * R + (kt >> 3);
                    int cnt = g_cnt[seg];
                    int off = g_off[seg];
                    if (cnt > 0) {
                        for (int i = 0; i < cnt; i++) {
                            int sidx = __ldg(&g_esrc[off + i]);
                            const float4* xp = (const float4*)(Xcur + (size_t)sidx * D + cbase);
                            #pragma unroll
                            for (int g = 0; g < 8; g++) {
                                float4 p = __ldg(xp + g);
                                v[g * 4 + 0] += p.x; v[g * 4 + 1] += p.y;
                                v[g * 4 + 2] += p.z; v[g * 4 + 3] += p.w;
                            }
                        }
                        float sc = 1.0f / (float)cnt;
                        #pragma unroll
                        for (int q = 0; q < 32; q++) v[q] *= sc;
                        if (ln) {
                            #pragma unroll
                            for (int q = 0; q < 32; q++)
                                v[q] = pw[cbase + q] * ((v[q] - mu) * rs) + pb[cbase + q];
                        }
                    }
                } else {
                    const float4* xp = (const float4*)(Xcur + (size_t)fnode * D + cbase);
                    #pragma unroll
                    for (int g = 0; g < 8; g++) {
                        float4 p = __ldg(xp + g);
                        v[g * 4 + 0] = p.x; v[g * 4 + 1] = p.y;
                        v[g * 4 + 2] = p.z; v[g * 4 + 3] = p.w;
                    }
                    if (ln) {
                        #pragma unroll
                        for (int q = 0; q < 32; q++)
                            v[q] = pw[cbase + q] * ((v[q] - mu) * rs) + pb[cbase + q];
                    }
                }
            }
            uint32_t* dst = (uint32_t*)(sm + s * STG + OA) + fn * LDAf;
            #pragma unroll
            for (int g = 0; g < 8; g++) {
                *(uint4*)(dst + g * 4) = make_uint4(
                    f2tf(v[g * 4 + 0]), f2tf(v[g * 4 + 1]),
                    f2tf(v[g * 4 + 2]), f2tf(v[g * 4 + 3]));
            }
            mbar_arrive(mb_afull + s * 8);
        }
        return;
    }

    // ================= CONSUMER: 256 threads, pure MMA =================
    int wm = wid & 1, wn = wid >> 1;
    float acc[4][8][4];
    #pragma unroll
    for (int i = 0; i < 4; i++)
        #pragma unroll
        for (int j = 0; j < 8; j++)
            #pragma unroll
            for (int q = 0; q < 4; q++) acc[i][j][q] = 0.f;

    int fr = lane >> 2, fc = lane & 3;

    #pragma unroll 1
    for (int kt = 0; kt < NST; kt++) {
        int b = kt % NSTAGE;
        uint32_t ph = (kt / 3) & 1;
        mbar_wait(mb_bfull + b * 8, ph);
        mbar_wait(mb_afull + b * 8, ph);

        const uint32_t* As = (const uint32_t*)(sm + b * STG + OA);
        const uint32_t* Bs = (const uint32_t*)(sm + b * STG + OB);

        #pragma unroll
        for (int kc = 0; kc < 4; kc++) {
            uint32_t a[4][4];
            #pragma unroll
            for (int mi = 0; mi < 4; mi++) {
                const uint32_t* Ab = As + (wm * 64 + mi * 16 + fr) * LDAf + kc * 8 + fc;
                a[mi][0] = Ab[0];
                a[mi][1] = Ab[8 * LDAf];
                a[mi][2] = Ab[4];
                a[mi][3] = Ab[8 * LDAf + 4];
            }
            #pragma unroll
            for (int nj = 0; nj < 8; nj++) {
                const uint32_t* Bb = Bs + (wn * 64 + nj * 8 + fr) * LDAf + kc * 8 + fc;
                uint32_t b0 = Bb[0], b1 = Bb[4];
                #pragma unroll
                for (int mi = 0; mi < 4; mi++)
                    mma_tf32(acc[mi][nj], a[mi], b0, b1);
            }
        }
        asm volatile("bar.sync 1, 256;" ::: "memory");
        if (tid == 0) {
            if (kt + NSTAGE < NST) {
                mbar_expect_tx(mb_bfull + b * 8, 36864);
                bulk_g2s(sbase + b * STG + OB, g_B + (size_t)(kt + NSTAGE) * BTILE,
                         36864, mb_bfull + b * 8);
            }
            mbar_arrive(mb_aempty + b * 8);
        }
    }

    // ---- epilogue: bias + residual(affine) + relu + stats ----
    float ps = 0.f, pq = 0.f;
    #pragma unroll
    for (int mi = 0; mi < 4; mi++) {
        #pragma unroll
        for (int half = 0; half < 2; half++) {
            int n = row0 + wm * 64 + mi * 16 + fr + half * 8;
            if (n >= Nn) continue;
            #pragma unroll
            for (int nj = 0; nj < 8; nj++) {
                int col = wn * 64 + nj * 8 + fc * 2;
                float2 xv = *(const float2*)(Xcur + (size_t)n * D + col);
                float2 bv = *(const float2*)(bconv + col);
                if (ln) {
                    float2 wv = *(const float2*)(pw + col);
                    float2 bb = *(const float2*)(pb + col);
                    xv.x = wv.x * ((xv.x - mu) * rs) + bb.x;
                    xv.y = wv.y * ((xv.y - mu) * rs) + bb.y;
                }
                float2 o;
                o.x = fmaxf(acc[mi][nj][half * 2 + 0] + bv.x + xv.x, 0.f);
                o.y = fmaxf(acc[mi][nj][half * 2 + 1] + bv.y + xv.y, 0.f);
                *(float2*)(Xnext + (size_t)n * D + col) = o;
                ps += o.x + o.y;
                pq += o.x * o.x + o.y * o.y;
            }
        }
    }
    if (statsOut != nullptr) {
        #pragma unroll
        for (int o = 16; o > 0; o >>= 1) {
            ps += __shfl_down_sync(0xffffffffu, ps, o);
            pq += __shfl_down_sync(0xffffffffu, pq, o);
        }
        if (lane == 0) {
            atomicAdd(&statsOut[0], (double)ps);
            atomicAdd(&statsOut[1], (double)pq);
        }
    }
}

// ---------------- global mean pool + head ----------------
__global__ void pool_cnt(const int* __restrict__ batch, int Nn) {
    int i = blockIdx.x * blockDim.x + threadIdx.x;
    if (i < Nn) atomicAdd(&g_gcnt[batch[i]], 1);
}
__global__ void pool_sum(const float* __restrict__ X, const int* __restrict__ batch, int Nn) {
    int idx = blockIdx.x * blockDim.x + threadIdx.x;
    if (idx >= Nn * (D / 4)) return;
    int n = idx >> 6, c = idx & 63;
    float4 v = ((const float4*)X)[(size_t)n * (D / 4) + c];
    red_add_v4(g_pool + batch[n] * D + c * 4, v);
}
__global__ void head_kernel(const float* __restrict__ W1, const float* __restrict__ b1,
                            const float* __restrict__ W2, const float* __restrict__ b2,
                            const float* __restrict__ W3, const float* __restrict__ b3,
                            float* __restrict__ out) {
    __shared__ float g[D], h1[D], h2[D];
    int bg = blockIdx.x, j = threadIdx.x;
    float c = fmaxf((float)g_gcnt[bg], 1.f);
    g[j] = g_pool[bg * D + j] / c;
    __syncthreads();
    float acc = b1[j];
    for (int k = 0; k < D; k++) acc = fmaf(g[k], W1[k * D + j], acc);
    h1[j] = fmaxf(acc, 0.f);
    __syncthreads();
    acc = b2[j];
    for (int k = 0; k < D; k++) acc = fmaf(h1[k], W2[k * D + j], acc);
    h2[j] = fmaxf(acc, 0.f);
    __syncthreads();
    if (j < 4) {
        acc = b3[j];
        for (int k = 0; k < D; k++) acc = fmaf(h2[k], W3[k * 4 + j], acc);
        out[bg * 4 + j] = acc;
    }
}

// ---------------- launch ----------------
extern "C" void kernel_launch(void* const* d_in, const int* in_sizes, int n_in,
                              void* d_out, int out_size) {
    const float* x      = (const float*)d_in[0];
    const int*   ei     = (const int*)d_in[1];
    const int*   et     = (const int*)d_in[2];
    const int*   batch  = (const int*)d_in[3];
    const float* W_rel  = (const float*)d_in[4];
    const float* W_root = (const float*)d_in[5];
    const float* b_conv = (const float*)d_in[6];
    const float* ln_w   = (const float*)d_in[7];
    const float* ln_b   = (const float*)d_in[8];
    const float* W1 = (const float*)d_in[9];
    const float* b1 = (const float*)d_in[10];
    const float* W2 = (const float*)d_in[11];
    const float* b2 = (const float*)d_in[12];
    const float* W3 = (const float*)d_in[13];
    const float* b3 = (const float*)d_in[14];

    int E  = in_sizes[1] / 2;
    int Nn = in_sizes[0] / D;
    int M  = Nn * D;
    const int* src = ei;
    const int* dst = ei + E;
    int L = Nn * R;
    int nb = (L + 255) / 256;

    cudaFuncSetAttribute(rgcn_fused, cudaFuncAttributeMaxDynamicSharedMemorySize, SMEM_TOTAL);

    void *pCnt, *pStats, *pPool, *pGcnt;
    cudaGetSymbolAddress(&pCnt, g_cnt);
    cudaGetSymbolAddress(&pStats, g_lnstats);
    cudaGetSymbolAddress(&pPool, g_pool);
    cudaGetSymbolAddress(&pGcnt, g_gcnt);
    double* pst = (double*)pStats;

    cudaMemsetAsync(pCnt, 0, (size_t)NMAX * R * sizeof(int));
    count_kernel<<<(E + 255) / 256, 256>>>(dst, et, E);
    scan_atomic<<<nb, 256>>>(L);
    place_kernel<<<(E + 255) / 256, 256>>>(src, dst, et, E);

    const float* cur = x;
    float* bufs[2];
    cudaGetSymbolAddress((void**)&bufs[0], g_X0);
    cudaGetSymbolAddress((void**)&bufs[1], g_X1);

    for (int l = 0; l < 3; l++) {
        const double* sp = (l > 0) ? (pst + (l - 1) * 2) : nullptr;
        const float* pw = (l > 0) ? (ln_w + (l - 1) * D) : nullptr;
        const float* pb = (l > 0) ? (ln_b + (l - 1) * D) : nullptr;
        prep_B<<<dim3(NST, D / 32), dim3(32, 8)>>>(
            W_rel + (size_t)l * R * D * D, W_root + (size_t)l * D * D);
        float* nxt = bufs[l & 1];
        double* so = (l < 2) ? (pst + l * 2) : nullptr;
        rgcn_fused<<<NBLK, 384, SMEM_TOTAL>>>(
            cur, b_conv + l * D, nxt, Nn, pw, pb, sp, so, M);
        cur = nxt;
    }

    cudaMemsetAsync(pPool, 0, NG * D * sizeof(float));
    cudaMemsetAsync(pGcnt, 0, NG * sizeof(int));
    pool_cnt<<<(Nn + 255) / 256, 256>>>(batch, Nn);
    pool_sum<<<(Nn * (D / 4) + 255) / 256, 256>>>(cur, batch, Nn);
    head_kernel<<<NG, D>>>(W1, b1, W2, b2, W3, b3, (float*)d_out);
}

// round 14
// speedup vs baseline: 2.0454x; 1.1429x over previous
#include <cuda_runtime.h>
#include <cuda_fp16.h>
#include <math.h>
#include <stdint.h>

#define D    256
#define R    8
#define NG   64
#define NMAX 50176          // 392*128
#define NBLK 392
#define EPS  1e-5f
#define KTOT 2304           // (R+1)*D
#define NST  72             // KTOT / 32
#define BM   128
#define EMAX 1048576

// fp16 tile geometry: rows of 32 halves padded to 40 (80B, ldmatrix conflict-free)
#define LDAH  40
#define ATILEB 10240                    // 128 * 80
#define BTILEB 20480                    // 256 * 80
#define BTILEH 10240                    // halves per B tile
#define OA    0
#define OB    10240
#define STG   30720
#define NSTAGE 4
#define SMEM_TOTAL (NSTAGE * STG + 128)

// ---------------- static device scratch ----------------
__device__ __half g_Bh[(size_t)NST * BTILEH];        // fp16 weights, tile-major K-major
__device__ float  g_X0[(size_t)NMAX * D];
__device__ float  g_X1[(size_t)NMAX * D];
__device__ int    g_cnt[NMAX * R];
__device__ int    g_off[NMAX * R];
__device__ int    g_pos[NMAX * R];
__device__ int    g_cursor[1];
__device__ int    g_esrc[EMAX];
__device__ double g_lnstats[3][2];
__device__ float  g_pool[NG * D];
__device__ int    g_gcnt[NG];

// ---------------- helpers ----------------
__device__ __forceinline__ uint32_t smem_u32(const void* p) {
    return (uint32_t)__cvta_generic_to_shared((void*)p);
}
__device__ __forceinline__ void red_add_v4(float* addr, float4 v) {
    asm volatile("red.global.add.v4.f32 [%0], {%1,%2,%3,%4};"
                 :: "l"(addr), "f"(v.x), "f"(v.y), "f"(v.z), "f"(v.w) : "memory");
}
__device__ __forceinline__ void ldsm4(uint32_t (&r)[4], uint32_t addr) {
    asm volatile("ldmatrix.sync.aligned.m8n8.x4.shared.b16 {%0,%1,%2,%3}, [%4];"
                 : "=r"(r[0]), "=r"(r[1]), "=r"(r[2]), "=r"(r[3]) : "r"(addr));
}
__device__ __forceinline__ void mma_f16(float (&d)[4], const uint32_t (&a)[4],
                                        uint32_t b0, uint32_t b1) {
    asm volatile(
        "mma.sync.aligned.m16n8k16.row.col.f32.f16.f16.f32 "
        "{%0,%1,%2,%3}, {%4,%5,%6,%7}, {%8,%9}, {%0,%1,%2,%3};"
        : "+f"(d[0]), "+f"(d[1]), "+f"(d[2]), "+f"(d[3])
        : "r"(a[0]), "r"(a[1]), "r"(a[2]), "r"(a[3]), "r"(b0), "r"(b1));
}
__device__ __forceinline__ void mbar_init(uint32_t mb, uint32_t cnt) {
    asm volatile("mbarrier.init.shared.b64 [%0], %1;" :: "r"(mb), "r"(cnt) : "memory");
}
__device__ __forceinline__ void mbar_arrive(uint32_t mb) {
    asm volatile("mbarrier.arrive.shared.b64 _, [%0];" :: "r"(mb) : "memory");
}
__device__ __forceinline__ void mbar_expect_tx(uint32_t mb, uint32_t bytes) {
    asm volatile("mbarrier.arrive.expect_tx.shared.b64 _, [%0], %1;"
                 :: "r"(mb), "r"(bytes) : "memory");
}
__device__ __forceinline__ void mbar_wait(uint32_t mb, uint32_t ph) {
    asm volatile(
        "{\n\t.reg .pred P;\n\t"
        "LW%=:\n\t"
        "mbarrier.try_wait.parity.acquire.cta.shared::cta.b64 P, [%0], %1, 0x989680;\n\t"
        "@P bra LD%=;\n\t"
        "bra LW%=;\n\t"
        "LD%=:\n\t}"
        :: "r"(mb), "r"(ph) : "memory");
}
__device__ __forceinline__ void bulk_g2s(uint32_t dst, const void* src,
                                         uint32_t bytes, uint32_t mb) {
    asm volatile(
        "cp.async.bulk.shared::cta.global.mbarrier::complete_tx::bytes [%0], [%1], %2, [%3];"
        :: "r"(dst), "l"(src), "r"(bytes), "r"(mb) : "memory");
}
__device__ __forceinline__ void ln_params(const double* st, int M, float& mu, float& rs) {
    double m = st[0] / (double)M;
    double var = st[1] / (double)M - m * m;
    mu = (float)m;
    rs = 1.0f / ((float)sqrt(fmax(var, 0.0)) + EPS);
}

// ---------------- CSR build ----------------
__global__ void count_kernel(const int* __restrict__ dst, const int* __restrict__ et, int E) {
    int i = blockIdx.x * blockDim.x + threadIdx.x;
    if (blockIdx.x == 0) {
        if (threadIdx.x < 6) ((double*)g_lnstats)[threadIdx.x] = 0.0;
        if (threadIdx.x == 6) g_cursor[0] = 0;
    }
    if (i < E) atomicAdd(&g_cnt[dst[i] * R + et[i]], 1);
}

__global__ void scan_atomic(int L) {
    __shared__ int sh[256];
    __shared__ int sbase;
    int tid = threadIdx.x;
    int i = blockIdx.x * 256 + tid;
    int v = (i < L) ? g_cnt[i] : 0;
    sh[tid] = v; __syncthreads();
    #pragma unroll
    for (int o = 1; o < 256; o <<= 1) {
        int t = (tid >= o) ? sh[tid - o] : 0;
        __syncthreads();
        sh[tid] += t;
        __syncthreads();
    }
    if (tid == 255) sbase = atomicAdd(&g_cursor[0], sh[255]);
    __syncthreads();
    if (i < L) {
        int o = sbase + sh[tid] - v;
        g_off[i] = o;
        g_pos[i] = o;
    }
}

__global__ void place_kernel(const int* __restrict__ src, const int* __restrict__ dst,
                             const int* __restrict__ et, int E) {
    int e = blockIdx.x * blockDim.x + threadIdx.x;
    if (e < E) {
        int seg = dst[e] * R + et[e];
        int p = atomicAdd(&g_pos[seg], 1);
        g_esrc[p] = src[e];
    }
}

// ---------------- weight prep: transpose + fp16 into tiled layout ----------------
__global__ void prep_B(const float* __restrict__ Wrel, const float* __restrict__ Wroot) {
    __shared__ float s[32][33];
    int k0 = blockIdx.x * 32, j0 = blockIdx.y * 32;
    int kt = blockIdx.x;
    for (int i = threadIdx.y; i < 32; i += 8) {
        int k = k0 + i;
        const float* row = (k < R * D) ? (Wrel + (size_t)k * D)
                                       : (Wroot + (size_t)(k - R * D) * D);
        s[i][threadIdx.x] = row[j0 + threadIdx.x];
    }
    __syncthreads();
    for (int i = threadIdx.y; i < 32; i += 8) {
        int j = j0 + i;
        g_Bh[(size_t)kt * BTILEH + j * LDAH + threadIdx.x] = __float2half_rn(s[threadIdx.x][i]);
    }
}

// ---------------- fused warp-specialized GEMM (fp16) ----------------
// 384 threads: warps 0-7 consumers (MMA), warps 8-11 producers (A gather).
__global__ __launch_bounds__(384, 1) void rgcn_fused(
    const float* __restrict__ Xcur,
    const float* __restrict__ bconv,
    float* __restrict__ Xnext, int Nn,
    const float* __restrict__ pw, const float* __restrict__ pb,
    const double* __restrict__ statsPrev,
    double* __restrict__ statsOut, int M)
{
    extern __shared__ char sm[];
    uint32_t sbase = smem_u32(sm);
    uint32_t mb_bfull  = sbase + NSTAGE * STG;        // 4 x 8B
    uint32_t mb_afull  = mb_bfull + 32;               // 4 x 8B
    uint32_t mb_aempty = mb_afull + 32;               // 4 x 8B
    int tid = threadIdx.x, lane = tid & 31, wid = tid >> 5;
    int row0 = blockIdx.x * BM;

    float mu = 0.f, rs = 0.f;
    bool ln = (statsPrev != nullptr);
    if (ln) ln_params(statsPrev, M, mu, rs);

    if (tid == 0) {
        #pragma unroll
        for (int s = 0; s < NSTAGE; s++) {
            mbar_init(mb_bfull + s * 8, 1);
            mbar_init(mb_afull + s * 8, 128);
            mbar_init(mb_aempty + s * 8, 1);
        }
    }
    __syncthreads();
    if (tid == 0) {
        #pragma unroll
        for (int s = 0; s < NSTAGE; s++) {
            mbar_expect_tx(mb_bfull + s * 8, BTILEB);
            bulk_g2s(sbase + s * STG + OB, g_Bh + (size_t)s * BTILEH, BTILEB, mb_bfull + s * 8);
        }
    }

    if (wid >= 8) {
        // ================= PRODUCER: 128 threads, one node each =================
        int fn = tid - 256;
        int fnode = row0 + fn;
        bool fvalid = fnode < Nn;
        #pragma unroll 1
        for (int kt = 0; kt < NST; kt++) {
            int s = kt % NSTAGE;
            if (kt >= NSTAGE)
                mbar_wait(mb_aempty + s * 8, ((kt / NSTAGE) + 1) & 1);
            float v[32];
            #pragma unroll
            for (int q = 0; q < 32; q++) v[q] = 0.f;
            int cbase = (kt < 64) ? ((kt & 7) * 32) : ((kt - 64) * 32);
            if (fvalid) {
                if (kt < 64) {
                    int seg = fnode * R + (kt >> 3);
                    int cnt = g_cnt[seg];
                    int off = g_off[seg];
                    if (cnt > 0) {
                        for (int i = 0; i < cnt; i++) {
                            int sidx = __ldg(&g_esrc[off + i]);
                            const float4* xp = (const float4*)(Xcur + (size_t)sidx * D + cbase);
                            #pragma unroll
                            for (int g = 0; g < 8; g++) {
                                float4 p = __ldg(xp + g);
                                v[g * 4 + 0] += p.x; v[g * 4 + 1] += p.y;
                                v[g * 4 + 2] += p.z; v[g * 4 + 3] += p.w;
                            }
                        }
                        float sc = 1.0f / (float)cnt;
                        #pragma unroll
                        for (int q = 0; q < 32; q++) v[q] *= sc;
                        if (ln) {
                            #pragma unroll
                            for (int q = 0; q < 32; q++)
                                v[q] = pw[cbase + q] * ((v[q] - mu) * rs) + pb[cbase + q];
                        }
                    }
                } else {
                    const float4* xp = (const float4*)(Xcur + (size_t)fnode * D + cbase);
                    #pragma unroll
                    for (int g = 0; g < 8; g++) {
                        float4 p = __ldg(xp + g);
                        v[g * 4 + 0] = p.x; v[g * 4 + 1] = p.y;
                        v[g * 4 + 2] = p.z; v[g * 4 + 3] = p.w;
                    }
                    if (ln) {
                        #pragma unroll
                        for (int q = 0; q < 32; q++)
                            v[q] = pw[cbase + q] * ((v[q] - mu) * rs) + pb[cbase + q];
                    }
                }
            }
            // pack to fp16x2 and store 4 x uint4
            uint32_t w16[16];
            #pragma unroll
            for (int p2 = 0; p2 < 16; p2++) {
                __half2 h = __floats2half2_rn(v[2 * p2], v[2 * p2 + 1]);
                w16[p2] = *reinterpret_cast<uint32_t*>(&h);
            }
            uint32_t* dst = (uint32_t*)(sm + s * STG + OA + fn * (LDAH * 2));
            *(uint4*)(dst + 0)  = make_uint4(w16[0],  w16[1],  w16[2],  w16[3]);
            *(uint4*)(dst + 4)  = make_uint4(w16[4],  w16[5],  w16[6],  w16[7]);
            *(uint4*)(dst + 8)  = make_uint4(w16[8],  w16[9],  w16[10], w16[11]);
            *(uint4*)(dst + 12) = make_uint4(w16[12], w16[13], w16[14], w16[15]);
            mbar_arrive(mb_afull + s * 8);
        }
        return;
    }

    // ================= CONSUMER: 256 threads, pure MMA =================
    int wm = wid & 1, wn = wid >> 1;
    float acc[4][8][4];
    #pragma unroll
    for (int i = 0; i < 4; i++)
        #pragma unroll
        for (int j = 0; j < 8; j++)
            #pragma unroll
            for (int q = 0; q < 4; q++) acc[i][j][q] = 0.f;

    uint32_t aoff = (uint32_t)((wm * 64 + (lane & 15)) * (LDAH * 2) + ((lane >> 4) << 4));
    uint32_t boff = (uint32_t)((wn * 64 + (lane & 15)) * (LDAH * 2) + ((lane >> 4) << 4));

    #pragma unroll 1
    for (int kt = 0; kt < NST; kt++) {
        int b = kt % NSTAGE;
        uint32_t ph = (kt / NSTAGE) & 1;
        mbar_wait(mb_bfull + b * 8, ph);
        mbar_wait(mb_afull + b * 8, ph);

        uint32_t sb = sbase + b * STG;
        #pragma unroll
        for (int ks = 0; ks < 2; ks++) {
            uint32_t koff = ks * 32;
            uint32_t ah[4][4];
            #pragma unroll
            for (int mi = 0; mi < 4; mi++)
                ldsm4(ah[mi], sb + OA + aoff + mi * 16 * (LDAH * 2) + koff);
            #pragma unroll
            for (int nj2 = 0; nj2 < 4; nj2++) {
                uint32_t bf[4];
                ldsm4(bf, sb + OB + boff + nj2 * 16 * (LDAH * 2) + koff);
                #pragma unroll
                for (int mi = 0; mi < 4; mi++) {
                    mma_f16(acc[mi][nj2 * 2],     ah[mi], bf[0], bf[2]);
                    mma_f16(acc[mi][nj2 * 2 + 1], ah[mi], bf[1], bf[3]);
                }
            }
        }
        asm volatile("bar.sync 1, 256;" ::: "memory");
        if (tid == 0) {
            if (kt + NSTAGE < NST) {
                mbar_expect_tx(mb_bfull + b * 8, BTILEB);
                bulk_g2s(sbase + b * STG + OB, g_Bh + (size_t)(kt + NSTAGE) * BTILEH,
                         BTILEB, mb_bfull + b * 8);
            }
            mbar_arrive(mb_aempty + b * 8);
        }
    }

    // ---- epilogue: bias + residual(affine) + relu + stats ----
    int fr = lane >> 2, fc = lane & 3;
    float ps = 0.f, pq = 0.f;
    #pragma unroll
    for (int mi = 0; mi < 4; mi++) {
        #pragma unroll
        for (int half = 0; half < 2; half++) {
            int n = row0 + wm * 64 + mi * 16 + fr + half * 8;
            if (n >= Nn) continue;
            #pragma unroll
            for (int nj = 0; nj < 8; nj++) {
                int col = wn * 64 + nj * 8 + fc * 2;
                float2 xv = *(const float2*)(Xcur + (size_t)n * D + col);
                float2 bv = *(const float2*)(bconv + col);
                if (ln) {
                    float2 wv = *(const float2*)(pw + col);
                    float2 bb = *(const float2*)(pb + col);
                    xv.x = wv.x * ((xv.x - mu) * rs) + bb.x;
                    xv.y = wv.y * ((xv.y - mu) * rs) + bb.y;
                }
                float2 o;
                o.x = fmaxf(acc[mi][nj][half * 2 + 0] + bv.x + xv.x, 0.f);
                o.y = fmaxf(acc[mi][nj][half * 2 + 1] + bv.y + xv.y, 0.f);
                *(float2*)(Xnext + (size_t)n * D + col) = o;
                ps += o.x + o.y;
                pq += o.x * o.x + o.y * o.y;
            }
        }
    }
    if (statsOut != nullptr) {
        #pragma unroll
        for (int o = 16; o > 0; o >>= 1) {
            ps += __shfl_down_sync(0xffffffffu, ps, o);
            pq += __shfl_down_sync(0xffffffffu, pq, o);
        }
        if (lane == 0) {
            atomicAdd(&statsOut[0], (double)ps);
            atomicAdd(&statsOut[1], (double)pq);
        }
    }
}

// ---------------- global mean pool + head ----------------
__global__ void pool_cnt(const int* __restrict__ batch, int Nn) {
    int i = blockIdx.x * blockDim.x + threadIdx.x;
    if (i < Nn) atomicAdd(&g_gcnt[batch[i]], 1);
}
__global__ void pool_sum(const float* __restrict__ X, const int* __restrict__ batch, int Nn) {
    int idx = blockIdx.x * blockDim.x + threadIdx.x;
    if (idx >= Nn * (D / 4)) return;
    int n = idx >> 6, c = idx & 63;
    float4 v = ((const float4*)X)[(size_t)n * (D / 4) + c];
    red_add_v4(g_pool + batch[n] * D + c * 4, v);
}
__global__ void head_kernel(const float* __restrict__ W1, const float* __restrict__ b1,
                            const float* __restrict__ W2, const float* __restrict__ b2,
                            const float* __restrict__ W3, const float* __restrict__ b3,
                            float* __restrict__ out) {
    __shared__ float g[D], h1[D], h2[D];
    int bg = blockIdx.x, j = threadIdx.x;
    float c = fmaxf((float)g_gcnt[bg], 1.f);
    g[j] = g_pool[bg * D + j] / c;
    __syncthreads();
    float acc = b1[j];
    for (int k = 0; k < D; k++) acc = fmaf(g[k], W1[k * D + j], acc);
    h1[j] = fmaxf(acc, 0.f);
    __syncthreads();
    acc = b2[j];
    for (int k = 0; k < D; k++) acc = fmaf(h1[k], W2[k * D + j], acc);
    h2[j] = fmaxf(acc, 0.f);
    __syncthreads();
    if (j < 4) {
        acc = b3[j];
        for (int k = 0; k < D; k++) acc = fmaf(h2[k], W3[k * 4 + j], acc);
        out[bg * 4 + j] = acc;
    }
}

// ---------------- launch ----------------
extern "C" void kernel_launch(void* const* d_in, const int* in_sizes, int n_in,
                              void* d_out, int out_size) {
    const float* x      = (const float*)d_in[0];
    const int*   ei     = (const int*)d_in[1];
    const int*   et     = (const int*)d_in[2];
    const int*   batch  = (const int*)d_in[3];
    const float* W_rel  = (const float*)d_in[4];
    const float* W_root = (const float*)d_in[5];
    const float* b_conv = (const float*)d_in[6];
    const float* ln_w   = (const float*)d_in[7];
    const float* ln_b   = (const float*)d_in[8];
    const float* W1 = (const float*)d_in[9];
    const float* b1 = (const float*)d_in[10];
    const float* W2 = (const float*)d_in[11];
    const float* b2 = (const float*)d_in[12];
    const float* W3 = (const float*)d_in[13];
    const float* b3 = (const float*)d_in[14];

    int E  = in_sizes[1] / 2;
    int Nn = in_sizes[0] / D;
    int M  = Nn * D;
    const int* src = ei;
    const int* dst = ei + E;
    int L = Nn * R;
    int nb = (L + 255) / 256;

    cudaFuncSetAttribute(rgcn_fused, cudaFuncAttributeMaxDynamicSharedMemorySize, SMEM_TOTAL);

    void *pCnt, *pStats, *pPool, *pGcnt;
    cudaGetSymbolAddress(&pCnt, g_cnt);
    cudaGetSymbolAddress(&pStats, g_lnstats);
    cudaGetSymbolAddress(&pPool, g_pool);
    cudaGetSymbolAddress(&pGcnt, g_gcnt);
    double* pst = (double*)pStats;

    cudaMemsetAsync(pCnt, 0, (size_t)NMAX * R * sizeof(int));
    count_kernel<<<(E + 255) / 256, 256>>>(dst, et, E);
    scan_atomic<<<nb, 256>>>(L);
    place_kernel<<<(E + 255) / 256, 256>>>(src, dst, et, E);

    const float* cur = x;
    float* bufs[2];
    cudaGetSymbolAddress((void**)&bufs[0], g_X0);
    cudaGetSymbolAddress((void**)&bufs[1], g_X1);

    for (int l = 0; l < 3; l++) {
        const double* sp = (l > 0) ? (pst + (l - 1) * 2) : nullptr;
        const float* pw = (l > 0) ? (ln_w + (l - 1) * D) : nullptr;
        const float* pb = (l > 0) ? (ln_b + (l - 1) * D) : nullptr;
        prep_B<<<dim3(NST, D / 32), dim3(32, 8)>>>(
            W_rel + (size_t)l * R * D * D, W_root + (size_t)l * D * D);
        float* nxt = bufs[l & 1];
        double* so = (l < 2) ? (pst + l * 2) : nullptr;
        rgcn_fused<<<NBLK, 384, SMEM_TOTAL>>>(
            cur, b_conv + l * D, nxt, Nn, pw, pb, sp, so, M);
        cur = nxt;
    }

    cudaMemsetAsync(pPool, 0, NG * D * sizeof(float));
    cudaMemsetAsync(pGcnt, 0, NG * sizeof(int));
    pool_cnt<<<(Nn + 255) / 256, 256>>>(batch, Nn);
    pool_sum<<<(Nn * (D / 4) + 255) / 256, 256>>>(cur, batch, Nn);
    head_kernel<<<NG, D>>>(W1, b1, W2, b2, W3, b3, (float*)d_out);
}

// round 15
// speedup vs baseline: 2.2783x; 1.1138x over previous
#include <cuda_runtime.h>
#include <cuda_fp16.h>
#include <math.h>
#include <stdint.h>

#define D    256
#define R    8
#define NG   64
#define NMAX 50176          // 392*128
#define NBLK 392
#define EPS  1e-5f
#define KTOT 2304           // (R+1)*D
#define NST  72             // KTOT / 32
#define BM   128
#define EMAX 1048576

// fp16 tile geometry: rows of 32 halves padded to 40 (80B, ldmatrix conflict-free)
#define LDAH  40
#define BTILEB 20480                    // bytes per B tile (256 * 80)
#define BTILEH 10240                    // halves per B tile
#define OA    0
#define OB    10240
#define STG   30720
#define NSTAGE 5
#define SMEM_TOTAL (NSTAGE * STG + 160)

// ---------------- static device scratch ----------------
__device__ __half g_Bh[(size_t)NST * BTILEH];        // fp16 weights, tile-major K-major
__device__ float  g_X0[(size_t)NMAX * D];
__device__ float  g_X1[(size_t)NMAX * D];
__device__ int    g_cnt[NMAX * R];
__device__ int    g_off[NMAX * R];
__device__ int    g_pos[NMAX * R];
__device__ int    g_cursor[1];
__device__ int    g_esrc[EMAX];
__device__ double g_lnstats[3][2];
__device__ float  g_pool[NG * D];
__device__ int    g_gcnt[NG];

// ---------------- helpers ----------------
__device__ __forceinline__ uint32_t smem_u32(const void* p) {
    return (uint32_t)__cvta_generic_to_shared((void*)p);
}
__device__ __forceinline__ void red_add_v4(float* addr, float4 v) {
    asm volatile("red.global.add.v4.f32 [%0], {%1,%2,%3,%4};"
                 :: "l"(addr), "f"(v.x), "f"(v.y), "f"(v.z), "f"(v.w) : "memory");
}
__device__ __forceinline__ void ldsm4(uint32_t (&r)[4], uint32_t addr) {
    asm volatile("ldmatrix.sync.aligned.m8n8.x4.shared.b16 {%0,%1,%2,%3}, [%4];"
                 : "=r"(r[0]), "=r"(r[1]), "=r"(r[2]), "=r"(r[3]) : "r"(addr));
}
__device__ __forceinline__ void mma_f16(float (&d)[4], const uint32_t (&a)[4],
                                        uint32_t b0, uint32_t b1) {
    asm volatile(
        "mma.sync.aligned.m16n8k16.row.col.f32.f16.f16.f32 "
        "{%0,%1,%2,%3}, {%4,%5,%6,%7}, {%8,%9}, {%0,%1,%2,%3};"
        : "+f"(d[0]), "+f"(d[1]), "+f"(d[2]), "+f"(d[3])
        : "r"(a[0]), "r"(a[1]), "r"(a[2]), "r"(a[3]), "r"(b0), "r"(b1));
}
__device__ __forceinline__ void mbar_init(uint32_t mb, uint32_t cnt) {
    asm volatile("mbarrier.init.shared.b64 [%0], %1;" :: "r"(mb), "r"(cnt) : "memory");
}
__device__ __forceinline__ void mbar_arrive(uint32_t mb) {
    asm volatile("mbarrier.arrive.shared.b64 _, [%0];" :: "r"(mb) : "memory");
}
__device__ __forceinline__ void mbar_expect_tx(uint32_t mb, uint32_t bytes) {
    asm volatile("mbarrier.arrive.expect_tx.shared.b64 _, [%0], %1;"
                 :: "r"(mb), "r"(bytes) : "memory");
}
__device__ __forceinline__ void mbar_wait(uint32_t mb, uint32_t ph) {
    asm volatile(
        "{\n\t.reg .pred P;\n\t"
        "LW%=:\n\t"
        "mbarrier.try_wait.parity.acquire.cta.shared::cta.b64 P, [%0], %1, 0x989680;\n\t"
        "@P bra LD%=;\n\t"
        "bra LW%=;\n\t"
        "LD%=:\n\t}"
        :: "r"(mb), "r"(ph) : "memory");
}
__device__ __forceinline__ void bulk_g2s(uint32_t dst, const void* src,
                                         uint32_t bytes, uint32_t mb) {
    asm volatile(
        "cp.async.bulk.shared::cta.global.mbarrier::complete_tx::bytes [%0], [%1], %2, [%3];"
        :: "r"(dst), "l"(src), "r"(bytes), "r"(mb) : "memory");
}
__device__ __forceinline__ void ln_params(const double* st, int M, float& mu, float& rs) {
    double m = st[0] / (double)M;
    double var = st[1] / (double)M - m * m;
    mu = (float)m;
    rs = 1.0f / ((float)sqrt(fmax(var, 0.0)) + EPS);
}

// ---------------- CSR build ----------------
__global__ void count_kernel(const int* __restrict__ dst, const int* __restrict__ et, int E) {
    int i = blockIdx.x * blockDim.x + threadIdx.x;
    if (blockIdx.x == 0) {
        if (threadIdx.x < 6) ((double*)g_lnstats)[threadIdx.x] = 0.0;
        if (threadIdx.x == 6) g_cursor[0] = 0;
    }
    if (i < E) atomicAdd(&g_cnt[dst[i] * R + et[i]], 1);
}

__global__ void scan_atomic(int L) {
    __shared__ int sh[256];
    __shared__ int sbase;
    int tid = threadIdx.x;
    int i = blockIdx.x * 256 + tid;
    int v = (i < L) ? g_cnt[i] : 0;
    sh[tid] = v; __syncthreads();
    #pragma unroll
    for (int o = 1; o < 256; o <<= 1) {
        int t = (tid >= o) ? sh[tid - o] : 0;
        __syncthreads();
        sh[tid] += t;
        __syncthreads();
    }
    if (tid == 255) sbase = atomicAdd(&g_cursor[0], sh[255]);
    __syncthreads();
    if (i < L) {
        int o = sbase + sh[tid] - v;
        g_off[i] = o;
        g_pos[i] = o;
    }
}

__global__ void place_kernel(const int* __restrict__ src, const int* __restrict__ dst,
                             const int* __restrict__ et, int E) {
    int e = blockIdx.x * blockDim.x + threadIdx.x;
    if (e < E) {
        int seg = dst[e] * R + et[e];
        int p = atomicAdd(&g_pos[seg], 1);
        g_esrc[p] = src[e];
    }
}

// ---------------- weight prep: transpose + fp16 into tiled layout ----------------
__global__ void prep_B(const float* __restrict__ Wrel, const float* __restrict__ Wroot) {
    __shared__ float s[32][33];
    int k0 = blockIdx.x * 32, j0 = blockIdx.y * 32;
    int kt = blockIdx.x;
    for (int i = threadIdx.y; i < 32; i += 8) {
        int k = k0 + i;
        const float* row = (k < R * D) ? (Wrel + (size_t)k * D)
                                       : (Wroot + (size_t)(k - R * D) * D);
        s[i][threadIdx.x] = row[j0 + threadIdx.x];
    }
    __syncthreads();
    for (int i = threadIdx.y; i < 32; i += 8) {
        int j = j0 + i;
        g_Bh[(size_t)kt * BTILEH + j * LDAH + threadIdx.x] = __float2half_rn(s[threadIdx.x][i]);
    }
}

// ---------------- fused warp-specialized GEMM (fp16, cached-index producer) ----------------
// 384 threads: warps 0-7 consumers (MMA), warps 8-11 producers (A gather).
__global__ __launch_bounds__(384, 1) void rgcn_fused(
    const float* __restrict__ Xcur,
    const float* __restrict__ bconv,
    float* __restrict__ Xnext, int Nn,
    const float* __restrict__ pw, const float* __restrict__ pb,
    const double* __restrict__ statsPrev,
    double* __restrict__ statsOut, int M)
{
    extern __shared__ char sm[];
    uint32_t sbase = smem_u32(sm);
    uint32_t mb_bfull  = sbase + NSTAGE * STG;        // 5 x 8B
    uint32_t mb_afull  = mb_bfull + 40;               // 5 x 8B
    uint32_t mb_aempty = mb_afull + 40;               // 5 x 8B
    int tid = threadIdx.x, lane = tid & 31, wid = tid >> 5;
    int row0 = blockIdx.x * BM;

    float mu = 0.f, rs = 0.f;
    bool ln = (statsPrev != nullptr);
    if (ln) ln_params(statsPrev, M, mu, rs);

    if (tid == 0) {
        #pragma unroll
        for (int s = 0; s < NSTAGE; s++) {
            mbar_init(mb_bfull + s * 8, 1);
            mbar_init(mb_afull + s * 8, 128);
            mbar_init(mb_aempty + s * 8, 1);
        }
    }
    __syncthreads();
    if (tid == 0) {
        #pragma unroll
        for (int s = 0; s < NSTAGE; s++) {
            mbar_expect_tx(mb_bfull + s * 8, BTILEB);
            bulk_g2s(sbase + s * STG + OB, g_Bh + (size_t)s * BTILEH, BTILEB, mb_bfull + s * 8);
        }
    }

    if (wid >= 8) {
        // ================= PRODUCER: 128 threads, one node each =================
        int fn = tid - 256;
        int fnode = row0 + fn;
        bool fvalid = fnode < Nn;

        // preload CSR metadata for all 8 relations of this node
        int pcnt[8], poff[8];
        #pragma unroll
        for (int r = 0; r < 8; r++) {
            pcnt[r] = fvalid ? __ldg(&g_cnt[fnode * R + r]) : 0;
            poff[r] = fvalid ? __ldg(&g_off[fnode * R + r]) : 0;
        }

        int cidx[8];
        int ccnt = 0, coff = 0;

        #pragma unroll 1
        for (int kt = 0; kt < NST; kt++) {
            int s = kt % NSTAGE;
            if (kt >= NSTAGE)
                mbar_wait(mb_aempty + s * 8, ((kt / NSTAGE) + 1) & 1);
            float v[32];
            #pragma unroll
            for (int q = 0; q < 32; q++) v[q] = 0.f;

            if (kt < 64) {
                int r = kt >> 3, ch = kt & 7;
                if (ch == 0) {
                    // refresh cached edge indices for this relation (parallel loads)
                    ccnt = pcnt[r];
                    coff = poff[r];
                    #pragma unroll
                    for (int i = 0; i < 8; i++)
                        cidx[i] = (i < ccnt) ? __ldg(&g_esrc[coff + i]) : 0;
                }
                int cbase = ch * 32;
                if (ccnt > 0) {
                    int i = 0;
                    int lim = (ccnt < 8) ? ccnt : 8;
                    // 2-edge unrolled: 16 independent float4 loads in flight
                    for (; i + 2 <= lim; i += 2) {
                        const float4* xa = (const float4*)(Xcur + (size_t)cidx[i] * D + cbase);
                        const float4* xb = (const float4*)(Xcur + (size_t)cidx[i + 1] * D + cbase);
                        #pragma unroll
                        for (int g = 0; g < 8; g++) {
                            float4 p = __ldg(xa + g);
                            float4 q = __ldg(xb + g);
                            v[g * 4 + 0] += p.x + q.x; v[g * 4 + 1] += p.y + q.y;
                            v[g * 4 + 2] += p.z + q.z; v[g * 4 + 3] += p.w + q.w;
                        }
                    }
                    if (i < lim) {
                        const float4* xa = (const float4*)(Xcur + (size_t)cidx[i] * D + cbase);
                        #pragma unroll
                        for (int g = 0; g < 8; g++) {
                            float4 p = __ldg(xa + g);
                            v[g * 4 + 0] += p.x; v[g * 4 + 1] += p.y;
                            v[g * 4 + 2] += p.z; v[g * 4 + 3] += p.w;
                        }
                    }
                    // slow path: rare high-degree tail
                    for (int j = 8; j < ccnt; j++) {
                        int sidx = __ldg(&g_esrc[coff + j]);
                        const float4* xa = (const float4*)(Xcur + (size_t)sidx * D + cbase);
                        #pragma unroll
                        for (int g = 0; g < 8; g++) {
                            float4 p = __ldg(xa + g);
                            v[g * 4 + 0] += p.x; v[g * 4 + 1] += p.y;
                            v[g * 4 + 2] += p.z; v[g * 4 + 3] += p.w;
                        }
                    }
                    float sc = 1.0f / (float)ccnt;
                    #pragma unroll
                    for (int q = 0; q < 32; q++) v[q] *= sc;
                    if (ln) {
                        #pragma unroll
                        for (int q = 0; q < 32; q++)
                            v[q] = pw[cbase + q] * ((v[q] - mu) * rs) + pb[cbase + q];
                    }
                }
            } else {
                int cbase = (kt - 64) * 32;
                if (fvalid) {
                    const float4* xp = (const float4*)(Xcur + (size_t)fnode * D + cbase);
                    #pragma unroll
                    for (int g = 0; g < 8; g++) {
                        float4 p = __ldg(xp + g);
                        v[g * 4 + 0] = p.x; v[g * 4 + 1] = p.y;
                        v[g * 4 + 2] = p.z; v[g * 4 + 3] = p.w;
                    }
                    if (ln) {
                        #pragma unroll
                        for (int q = 0; q < 32; q++)
                            v[q] = pw[cbase + q] * ((v[q] - mu) * rs) + pb[cbase + q];
                    }
                }
            }
            // pack to fp16x2 and store 4 x uint4
            uint32_t w16[16];
            #pragma unroll
            for (int p2 = 0; p2 < 16; p2++) {
                __half2 h = __floats2half2_rn(v[2 * p2], v[2 * p2 + 1]);
                w16[p2] = *reinterpret_cast<uint32_t*>(&h);
            }
            uint32_t* dst = (uint32_t*)(sm + s * STG + OA + fn * (LDAH * 2));
            *(uint4*)(dst + 0)  = make_uint4(w16[0],  w16[1],  w16[2],  w16[3]);
            *(uint4*)(dst + 4)  = make_uint4(w16[4],  w16[5],  w16[6],  w16[7]);
            *(uint4*)(dst + 8)  = make_uint4(w16[8],  w16[9],  w16[10], w16[11]);
            *(uint4*)(dst + 12) = make_uint4(w16[12], w16[13], w16[14], w16[15]);
            mbar_arrive(mb_afull + s * 8);
        }
        return;
    }

    // ================= CONSUMER: 256 threads, pure MMA =================
    int wm = wid & 1, wn = wid >> 1;
    float acc[4][8][4];
    #pragma unroll
    for (int i = 0; i < 4; i++)
        #pragma unroll
        for (int j = 0; j < 8; j++)
            #pragma unroll
            for (int q = 0; q < 4; q++) acc[i][j][q] = 0.f;

    uint32_t aoff = (uint32_t)((wm * 64 + (lane & 15)) * (LDAH * 2) + ((lane >> 4) << 4));
    uint32_t boff = (uint32_t)((wn * 64 + (lane & 15)) * (LDAH * 2) + ((lane >> 4) << 4));

    #pragma unroll 1
    for (int kt = 0; kt < NST; kt++) {
        int b = kt % NSTAGE;
        uint32_t ph = (kt / NSTAGE) & 1;
        mbar_wait(mb_bfull + b * 8, ph);
        mbar_wait(mb_afull + b * 8, ph);

        uint32_t sb = sbase + b * STG;
        #pragma unroll
        for (int ks = 0; ks < 2; ks++) {
            uint32_t koff = ks * 32;
            uint32_t ah[4][4];
            #pragma unroll
            for (int mi = 0; mi < 4; mi++)
                ldsm4(ah[mi], sb + OA + aoff + mi * 16 * (LDAH * 2) + koff);
            #pragma unroll
            for (int nj2 = 0; nj2 < 4; nj2++) {
                uint32_t bf[4];
                ldsm4(bf, sb + OB + boff + nj2 * 16 * (LDAH * 2) + koff);
                #pragma unroll
                for (int mi = 0; mi < 4; mi++) {
                    mma_f16(acc[mi][nj2 * 2],     ah[mi], bf[0], bf[2]);
                    mma_f16(acc[mi][nj2 * 2 + 1], ah[mi], bf[1], bf[3]);
                }
            }
        }
        asm volatile("bar.sync 1, 256;" ::: "memory");
        if (tid == 0) {
            if (kt + NSTAGE < NST) {
                mbar_expect_tx(mb_bfull + b * 8, BTILEB);
                bulk_g2s(sbase + b * STG + OB, g_Bh + (size_t)(kt + NSTAGE) * BTILEH,
                         BTILEB, mb_bfull + b * 8);
            }
            mbar_arrive(mb_aempty + b * 8);
        }
    }

    // ---- epilogue: bias + residual(affine) + relu + stats ----
    int fr = lane >> 2, fc = lane & 3;
    float ps = 0.f, pq = 0.f;
    #pragma unroll
    for (int mi = 0; mi < 4; mi++) {
        #pragma unroll
        for (int half = 0; half < 2; half++) {
            int n = row0 + wm * 64 + mi * 16 + fr + half * 8;
            if (n >= Nn) continue;
            #pragma unroll
            for (int nj = 0; nj < 8; nj++) {
                int col = wn * 64 + nj * 8 + fc * 2;
                float2 xv = *(const float2*)(Xcur + (size_t)n * D + col);
                float2 bv = *(const float2*)(bconv + col);
                if (ln) {
                    float2 wv = *(const float2*)(pw + col);
                    float2 bb = *(const float2*)(pb + col);
                    xv.x = wv.x * ((xv.x - mu) * rs) + bb.x;
                    xv.y = wv.y * ((xv.y - mu) * rs) + bb.y;
                }
                float2 o;
                o.x = fmaxf(acc[mi][nj][half * 2 + 0] + bv.x + xv.x, 0.f);
                o.y = fmaxf(acc[mi][nj][half * 2 + 1] + bv.y + xv.y, 0.f);
                *(float2*)(Xnext + (size_t)n * D + col) = o;
                ps += o.x + o.y;
                pq += o.x * o.x + o.y * o.y;
            }
        }
    }
    if (statsOut != nullptr) {
        #pragma unroll
        for (int o = 16; o > 0; o >>= 1) {
            ps += __shfl_down_sync(0xffffffffu, ps, o);
            pq += __shfl_down_sync(0xffffffffu, pq, o);
        }
        if (lane == 0) {
            atomicAdd(&statsOut[0], (double)ps);
            atomicAdd(&statsOut[1], (double)pq);
        }
    }
}

// ---------------- global mean pool + head ----------------
__global__ void pool_cnt(const int* __restrict__ batch, int Nn) {
    int i = blockIdx.x * blockDim.x + threadIdx.x;
    if (i < Nn) atomicAdd(&g_gcnt[batch[i]], 1);
}
__global__ void pool_sum(const float* __restrict__ X, const int* __restrict__ batch, int Nn) {
    int idx = blockIdx.x * blockDim.x + threadIdx.x;
    if (idx >= Nn * (D / 4)) return;
    int n = idx >> 6, c = idx & 63;
    float4 v = ((const float4*)X)[(size_t)n * (D / 4) + c];
    red_add_v4(g_pool + batch[n] * D + c * 4, v);
}
__global__ void head_kernel(const float* __restrict__ W1, const float* __restrict__ b1,
                            const float* __restrict__ W2, const float* __restrict__ b2,
                            const float* __restrict__ W3, const float* __restrict__ b3,
                            float* __restrict__ out) {
    __shared__ float g[D], h1[D], h2[D];
    int bg = blockIdx.x, j = threadIdx.x;
    float c = fmaxf((float)g_gcnt[bg], 1.f);
    g[j] = g_pool[bg * D + j] / c;
    __syncthreads();
    float acc = b1[j];
    for (int k = 0; k < D; k++) acc = fmaf(g[k], W1[k * D + j], acc);
    h1[j] = fmaxf(acc, 0.f);
    __syncthreads();
    acc = b2[j];
    for (int k = 0; k < D; k++) acc = fmaf(h1[k], W2[k * D + j], acc);
    h2[j] = fmaxf(acc, 0.f);
    __syncthreads();
    if (j < 4) {
        acc = b3[j];
        for (int k = 0; k < D; k++) acc = fmaf(h2[k], W3[k * 4 + j], acc);
        out[bg * 4 + j] = acc;
    }
}

// ---------------- launch ----------------
extern "C" void kernel_launch(void* const* d_in, const int* in_sizes, int n_in,
                              void* d_out, int out_size) {
    const float* x      = (const float*)d_in[0];
    const int*   ei     = (const int*)d_in[1];
    const int*   et     = (const int*)d_in[2];
    const int*   batch  = (const int*)d_in[3];
    const float* W_rel  = (const float*)d_in[4];
    const float* W_root = (const float*)d_in[5];
    const float* b_conv = (const float*)d_in[6];
    const float* ln_w   = (const float*)d_in[7];
    const float* ln_b   = (const float*)d_in[8];
    const float* W1 = (const float*)d_in[9];
    const float* b1 = (const float*)d_in[10];
    const float* W2 = (const float*)d_in[11];
    const float* b2 = (const float*)d_in[12];
    const float* W3 = (const float*)d_in[13];
    const float* b3 = (const float*)d_in[14];

    int E  = in_sizes[1] / 2;
    int Nn = in_sizes[0] / D;
    int M  = Nn * D;
    const int* src = ei;
    const int* dst = ei + E;
    int L = Nn * R;
    int nb = (L + 255) / 256;

    cudaFuncSetAttribute(rgcn_fused, cudaFuncAttributeMaxDynamicSharedMemorySize, SMEM_TOTAL);

    void *pCnt, *pStats, *pPool, *pGcnt;
    cudaGetSymbolAddress(&pCnt, g_cnt);
    cudaGetSymbolAddress(&pStats, g_lnstats);
    cudaGetSymbolAddress(&pPool, g_pool);
    cudaGetSymbolAddress(&pGcnt, g_gcnt);
    double* pst = (double*)pStats;

    cudaMemsetAsync(pCnt, 0, (size_t)NMAX * R * sizeof(int));
    count_kernel<<<(E + 255) / 256, 256>>>(dst, et, E);
    scan_atomic<<<nb, 256>>>(L);
    place_kernel<<<(E + 255) / 256, 256>>>(src, dst, et, E);

    const float* cur = x;
    float* bufs[2];
    cudaGetSymbolAddress((void**)&bufs[0], g_X0);
    cudaGetSymbolAddress((void**)&bufs[1], g_X1);

    for (int l = 0; l < 3; l++) {
        const double* sp = (l > 0) ? (pst + (l - 1) * 2) : nullptr;
        const float* pw = (l > 0) ? (ln_w + (l - 1) * D) : nullptr;
        const float* pb = (l > 0) ? (ln_b + (l - 1) * D) : nullptr;
        prep_B<<<dim3(NST, D / 32), dim3(32, 8)>>>(
            W_rel + (size_t)l * R * D * D, W_root + (size_t)l * D * D);
        float* nxt = bufs[l & 1];
        double* so = (l < 2) ? (pst + l * 2) : nullptr;
        rgcn_fused<<<NBLK, 384, SMEM_TOTAL>>>(
            cur, b_conv + l * D, nxt, Nn, pw, pb, sp, so, M);
        cur = nxt;
    }

    cudaMemsetAsync(pPool, 0, NG * D * sizeof(float));
    cudaMemsetAsync(pGcnt, 0, NG * sizeof(int));
    pool_cnt<<<(Nn + 255) / 256, 256>>>(batch, Nn);
    pool_sum<<<(Nn * (D / 4) + 255) / 256, 256>>>(cur, batch, Nn);
    head_kernel<<<NG, D>>>(W1, b1, W2, b2, W3, b3, (float*)d_out);
}